// round 11
// baseline (speedup 1.0000x reference)
#include <cuda_runtime.h>
#include <cstdint>

#define BB 1024
#define TT 512
#define HHH 64
#define NGRP 128           // batch row-groups of 8

typedef unsigned long long ull;

// Scratch (device globals — allocation-free per harness rules)
// gx streams in PRODUCER-THREAD order: idx = (t*NGRP + bgrp)*512 + tid
__device__ ull   g_gxz[(size_t)TT * NGRP * 512];   // (xr,xz) packed, 256 MiB
__device__ float g_gxn[(size_t)TT * NGRP * 512];   // xn, 128 MiB
__device__ float g_bufA[(size_t)TT * BB * HHH];    // layer0 outputs [t][b][64]
__device__ float g_bufB[(size_t)TT * BB * HHH];    // layer1 outputs [t][b][64]
__device__ float g_hlast[BB * HHH];                // layer2 final h

// ---- f32x2 packed helpers ----
__device__ __forceinline__ ull pk2(float lo, float hi) {
    ull r; asm("mov.b64 %0, {%1, %2};" : "=l"(r) : "f"(lo), "f"(hi)); return r;
}
__device__ __forceinline__ void upk2(ull v, float& lo, float& hi) {
    asm("mov.b64 {%0, %1}, %2;" : "=f"(lo), "=f"(hi) : "l"(v));
}
__device__ __forceinline__ ull fma2(ull a, ull b, ull c) {
    ull d; asm("fma.rn.f32x2 %0, %1, %2, %3;" : "=l"(d) : "l"(a), "l"(b), "l"(c)); return d;
}
__device__ __forceinline__ ull add2(ull a, ull b) {
    ull d; asm("add.rn.f32x2 %0, %1, %2;" : "=l"(d) : "l"(a), "l"(b)); return d;
}
__device__ __forceinline__ float hsum2(ull v) {
    float lo, hi; upk2(v, lo, hi); return lo + hi;
}
__device__ __forceinline__ float fsigmoid(float x) {
    return __fdividef(1.0f, 1.0f + __expf(-x));
}
__device__ __forceinline__ float ftanhf(float x) {
    float e = __expf(2.0f * x);
    return 1.0f - __fdividef(2.0f, e + 1.0f);
}
__device__ __forceinline__ int P72(int k) { return k + 4 * (k >> 5); }

// ---------------------------------------------------------------------------
// x-projection kernel (barrier-free, no smem). 2048 blocks x 512 threads.
// Block: bgrp = blk & 127 (8 batch rows), t-chunk = blk >> 7 (32 timesteps).
// Thread (tau=(lane&3)|(warp<<2), s=lane>>2): W_ih slice (3 gates x k[8s,8s+8))
// in registers; per t: dot over 8 rows (2 passes of 4), shfl transpose-reduce,
// thread ends with (xr,xz,xn)+bias for (ROWN, tau); writes gx streams in
// producer-thread order (coalesced 256B/128B per warp).
// INW = 16: x is [b][t][16]; INW = 64: input is [t][b][64].
// ---------------------------------------------------------------------------
template <int INW>
__global__ void __launch_bounds__(512, 1) gx_proj(
    const float* __restrict__ xin,
    const float* __restrict__ Wih, const float* __restrict__ bih)
{
    const int tid  = threadIdx.x;
    const int warp = tid >> 5;
    const int lane = tid & 31;
    const int tau  = (lane & 3) | (warp << 2);
    const int s    = lane >> 2;
    const int sb0  = s & 1, sb1 = (s >> 1) & 1, sb2 = s >> 2;
    const int bgrp = blockIdx.x & (NGRP - 1);
    const int tc   = blockIdx.x >> 7;          // 0..15
    const int b0   = bgrp * 8;

    constexpr int NXU = (INW == 64) ? 4 : 1;
    ull wx[3][NXU];
    if (INW == 64) {
#pragma unroll
        for (int g = 0; g < 3; g++)
#pragma unroll
            for (int kp = 0; kp < 4; kp++)
                wx[g][kp] = *(const ull*)(Wih + (size_t)(g * 64 + tau) * 64 + 8 * s + 2 * kp);
    } else {
#pragma unroll
        for (int g = 0; g < 3; g++)
            wx[g][0] = *(const ull*)(Wih + (size_t)(g * 64 + tau) * 16 + 2 * s);
    }
    const float bXr = __ldg(bih + tau);
    const float bXz = __ldg(bih + 64 + tau);
    const float bXn = __ldg(bih + 128 + tau);

#pragma unroll 1
    for (int ti = 0; ti < 32; ++ti) {
        const int t = tc * 32 + ti;
        float fr, fz, fn;
#pragma unroll
        for (int p = 0; p < 2; p++) {
            ull aR[4], aZ[4], aN[4];
#pragma unroll
            for (int r = 0; r < 4; r++) { aR[r] = 0; aZ[r] = 0; aN[r] = 0; }
#pragma unroll
            for (int r = 0; r < 4; r++) {
                const int row = p * 4 + r;
                if (INW == 64) {
                    const ulonglong2* xq = (const ulonglong2*)
                        (xin + ((size_t)t * BB + b0 + row) * 64 + 8 * s);
                    ulonglong2 C = __ldg(xq), D = __ldg(xq + 1);
                    aR[r] = fma2(wx[0][0], C.x, aR[r]); aR[r] = fma2(wx[0][1], C.y, aR[r]);
                    aR[r] = fma2(wx[0][2], D.x, aR[r]); aR[r] = fma2(wx[0][3], D.y, aR[r]);
                    aZ[r] = fma2(wx[1][0], C.x, aZ[r]); aZ[r] = fma2(wx[1][1], C.y, aZ[r]);
                    aZ[r] = fma2(wx[1][2], D.x, aZ[r]); aZ[r] = fma2(wx[1][3], D.y, aZ[r]);
                    aN[r] = fma2(wx[2][0], C.x, aN[r]); aN[r] = fma2(wx[2][1], C.y, aN[r]);
                    aN[r] = fma2(wx[2][2], D.x, aN[r]); aN[r] = fma2(wx[2][3], D.y, aN[r]);
                } else {
                    ull xv = __ldg((const ull*)
                        (xin + ((size_t)(b0 + row) * TT + t) * 16 + 2 * s));
                    aR[r] = fma2(wx[0][0], xv, aR[r]);
                    aZ[r] = fma2(wx[1][0], xv, aZ[r]);
                    aN[r] = fma2(wx[2][0], xv, aN[r]);
                }
            }
#pragma unroll
            for (int pl = 0; pl < 3; pl++) {
                ull* a = (pl == 0) ? aR : (pl == 1) ? aZ : aN;
                ull s0v = sb0 ? a[0] : a[2];
                ull s1v = sb0 ? a[1] : a[3];
                ull r0v = __shfl_xor_sync(0xffffffffu, s0v, 4);
                ull r1v = __shfl_xor_sync(0xffffffffu, s1v, 4);
                ull b0v = add2(sb0 ? a[2] : a[0], r0v);
                ull b1v = add2(sb0 ? a[3] : a[1], r1v);
                ull s2v = sb1 ? b0v : b1v;
                ull r2v = __shfl_xor_sync(0xffffffffu, s2v, 8);
                ull cv  = add2(sb1 ? b1v : b0v, r2v);
                ull dv  = add2(cv, __shfl_xor_sync(0xffffffffu, cv, 16));
                if (p == sb2) {
                    float v = hsum2(dv);
                    if (pl == 0) fr = v; else if (pl == 1) fz = v; else fn = v;
                }
            }
        }
        const size_t idx = ((size_t)t * NGRP + bgrp) * 512 + tid;
        g_gxz[idx] = pk2(fr + bXr, fz + bXz);
        g_gxn[idx] = fn + bXn;
    }
}

// ---------------------------------------------------------------------------
// Recurrent GRU layer (hh only; x-projection read from gx streams).
// 128 blocks x 512 threads; block owns rows [8*blk, 8*blk+8).
// Same thread map as gx_proj, so gx reads are 1 coalesced ull + 1 float.
// One barrier per step; h published via ping-pong swizzled hbuf; output
// written coalesced from hbuf one step later.
// WALL = 1: all timesteps -> outbuf; 0: final h only.
// ---------------------------------------------------------------------------
template <int WALL>
__global__ void __launch_bounds__(512, 1) gru_rec(
    const float* __restrict__ Whh, const float* __restrict__ bhh,
    float* __restrict__ outbuf)
{
    __shared__ float hbuf[2][8 * 72];

    const int tid  = threadIdx.x;
    const int warp = tid >> 5;
    const int lane = tid & 31;
    const int tau  = (lane & 3) | (warp << 2);
    const int s    = lane >> 2;
    const int sb0  = s & 1, sb1 = (s >> 1) & 1, sb2 = s >> 2;
    const int ROWN = 4 * sb2 + 2 * sb0 + sb1;
    const int bx   = blockIdx.x;
    const int b0   = bx * 8;
    const int hoff = 8 * s + 4 * (s >> 2);

    ull wh[3][4];
#pragma unroll
    for (int g = 0; g < 3; g++)
#pragma unroll
        for (int kp = 0; kp < 4; kp++)
            wh[g][kp] = *(const ull*)(Whh + (size_t)(g * 64 + tau) * 64 + 8 * s + 2 * kp);

    const float bR  = __ldg(bhh + tau);
    const float bZ  = __ldg(bhh + 64 + tau);
    const float bNh = __ldg(bhh + 128 + tau);

    for (int e = tid; e < 2 * 8 * 72; e += 512) ((float*)hbuf)[e] = 0.0f;

    const int orow = tid >> 6;
    const int ocol = tid & 63;
    const int ostride = P72(ocol);

    float h = 0.0f;
    // gx for t=0
    ull   gz = __ldg(g_gxz + ((size_t)0 * NGRP + bx) * 512 + tid);
    float gn = __ldg(g_gxn + ((size_t)0 * NGRP + bx) * 512 + tid);
    __syncthreads();

#pragma unroll 1
    for (int t = 0; t < TT; ++t) {
        const int cur = t & 1;
        const float* hb = hbuf[cur];

        // prefetch next gx (hidden under dot phase)
        const int tn = (t + 1 < TT) ? t + 1 : t;
        const size_t gidx = ((size_t)tn * NGRP + bx) * 512 + tid;
        ull   gz2 = __ldg(g_gxz + gidx);
        float gn2 = __ldg(g_gxn + gidx);

        // deferred coalesced out-store of h(t-1)
        if (WALL && t > 0) {
            outbuf[((size_t)(t - 1) * BB + b0 + orow) * 64 + ocol] =
                hb[orow * 72 + ostride];
        }

        // ---- dot + reduce over h ----
        float fr, fz, fnh;
#pragma unroll
        for (int p = 0; p < 2; p++) {
            ull aR[4], aZ[4], aNh[4];
#pragma unroll
            for (int r = 0; r < 4; r++) { aR[r] = 0; aZ[r] = 0; aNh[r] = 0; }
#pragma unroll
            for (int r = 0; r < 4; r++) {
                const int row = p * 4 + r;
                const ulonglong2* hq = (const ulonglong2*)(hb + row * 72 + hoff);
                ulonglong2 A = hq[0], B = hq[1];
                aR[r]  = fma2(wh[0][0], A.x, aR[r]);  aR[r]  = fma2(wh[0][1], A.y, aR[r]);
                aR[r]  = fma2(wh[0][2], B.x, aR[r]);  aR[r]  = fma2(wh[0][3], B.y, aR[r]);
                aZ[r]  = fma2(wh[1][0], A.x, aZ[r]);  aZ[r]  = fma2(wh[1][1], A.y, aZ[r]);
                aZ[r]  = fma2(wh[1][2], B.x, aZ[r]);  aZ[r]  = fma2(wh[1][3], B.y, aZ[r]);
                aNh[r] = fma2(wh[2][0], A.x, aNh[r]); aNh[r] = fma2(wh[2][1], A.y, aNh[r]);
                aNh[r] = fma2(wh[2][2], B.x, aNh[r]); aNh[r] = fma2(wh[2][3], B.y, aNh[r]);
            }
#pragma unroll
            for (int pl = 0; pl < 3; pl++) {
                ull* a = (pl == 0) ? aR : (pl == 1) ? aZ : aNh;
                ull s0v = sb0 ? a[0] : a[2];
                ull s1v = sb0 ? a[1] : a[3];
                ull r0v = __shfl_xor_sync(0xffffffffu, s0v, 4);
                ull r1v = __shfl_xor_sync(0xffffffffu, s1v, 4);
                ull b0v = add2(sb0 ? a[2] : a[0], r0v);
                ull b1v = add2(sb0 ? a[3] : a[1], r1v);
                ull s2v = sb1 ? b0v : b1v;
                ull r2v = __shfl_xor_sync(0xffffffffu, s2v, 8);
                ull cv  = add2(sb1 ? b1v : b0v, r2v);
                ull dv  = add2(cv, __shfl_xor_sync(0xffffffffu, cv, 16));
                if (p == sb2) {
                    float v = hsum2(dv);
                    if (pl == 0) fr = v; else if (pl == 1) fz = v; else fnh = v;
                }
            }
        }

        // ---- update (in-register h) ----
        float xr, xz; upk2(gz, xr, xz);
        float r = fsigmoid(xr + fr + bR);
        float z = fsigmoid(xz + fz + bZ);
        float n = ftanhf(gn + r * (fnh + bNh));
        h = fmaf(z, h - n, n);

        hbuf[cur ^ 1][ROWN * 72 + P72(tau)] = h;
        gz = gz2; gn = gn2;
        __syncthreads();
    }

    if (WALL) {
        outbuf[((size_t)(TT - 1) * BB + b0 + orow) * 64 + ocol] =
            hbuf[0][orow * 72 + ostride];
    } else {
        outbuf[(size_t)(b0 + orow) * 64 + ocol] = hbuf[0][orow * 72 + ostride];
    }
}

// ---------------------------------------------------------------------------
// Head: y[b] = fc2_b + fc2_w . relu(fc1_w @ h_last[b] + fc1_b)
// ---------------------------------------------------------------------------
__global__ void __launch_bounds__(256) head_kernel(
    const float* __restrict__ fc1w, const float* __restrict__ fc1b,
    const float* __restrict__ fc2w, const float* __restrict__ fc2b,
    float* __restrict__ y)
{
    __shared__ float s1[32 * 64];
    __shared__ float sb1[32];
    __shared__ float sw2[32];
    const int tid = threadIdx.x;
    for (int e = tid; e < 2048; e += 256) s1[e] = fc1w[e];
    if (tid < 32) { sb1[tid] = fc1b[tid]; sw2[tid] = fc2w[tid]; }
    __syncthreads();

    const int b = blockIdx.x * 256 + tid;
    const float* hp = g_hlast + (size_t)b * HHH;
    float hv[64];
#pragma unroll
    for (int q = 0; q < 16; q++) {
        float4 v = *(const float4*)(hp + q * 4);
        hv[q * 4] = v.x; hv[q * 4 + 1] = v.y; hv[q * 4 + 2] = v.z; hv[q * 4 + 3] = v.w;
    }
    float acc = __ldg(fc2b);
#pragma unroll
    for (int j = 0; j < 32; j++) {
        float sacc = sb1[j];
#pragma unroll
        for (int k = 0; k < 64; k++) sacc = fmaf(s1[j * 64 + k], hv[k], sacc);
        acc = fmaf(sw2[j], fmaxf(sacc, 0.0f), acc);
    }
    y[b] = acc;
}

// ---------------------------------------------------------------------------
extern "C" void kernel_launch(void* const* d_in, const int* in_sizes, int n_in,
                              void* d_out, int out_size)
{
    const float* x    = (const float*)d_in[0];
    const float* Wih0 = (const float*)d_in[1];
    const float* Whh0 = (const float*)d_in[2];
    const float* bih0 = (const float*)d_in[3];
    const float* bhh0 = (const float*)d_in[4];
    const float* Wih1 = (const float*)d_in[5];
    const float* Whh1 = (const float*)d_in[6];
    const float* bih1 = (const float*)d_in[7];
    const float* bhh1 = (const float*)d_in[8];
    const float* Wih2 = (const float*)d_in[9];
    const float* Whh2 = (const float*)d_in[10];
    const float* bih2 = (const float*)d_in[11];
    const float* bhh2 = (const float*)d_in[12];
    const float* fc1w = (const float*)d_in[13];
    const float* fc1b = (const float*)d_in[14];
    const float* fc2w = (const float*)d_in[15];
    const float* fc2b = (const float*)d_in[16];
    float* y = (float*)d_out;
    (void)in_sizes; (void)n_in; (void)out_size;

    float *bufA = nullptr, *bufB = nullptr, *hlast = nullptr;
    cudaGetSymbolAddress((void**)&bufA, g_bufA);
    cudaGetSymbolAddress((void**)&bufB, g_bufB);
    cudaGetSymbolAddress((void**)&hlast, g_hlast);

    // layer 0
    gx_proj<16><<<2048, 512>>>(x, Wih0, bih0);
    gru_rec<1><<<128, 512>>>(Whh0, bhh0, bufA);
    // layer 1
    gx_proj<64><<<2048, 512>>>(bufA, Wih1, bih1);
    gru_rec<1><<<128, 512>>>(Whh1, bhh1, bufB);
    // layer 2
    gx_proj<64><<<2048, 512>>>(bufB, Wih2, bih2);
    gru_rec<0><<<128, 512>>>(Whh2, bhh2, hlast);
    // head
    head_kernel<<<4, 256>>>(fc1w, fc1b, fc2w, fc2b, y);
}

// round 12
// speedup vs baseline: 1.1017x; 1.1017x over previous
#include <cuda_runtime.h>
#include <cstdint>

#define BB 1024
#define TT 512
#define HHH 64

typedef unsigned long long ull;

// Scratch (device globals — allocation-free per harness rules)
__device__ float g_bufA[(size_t)TT * BB * HHH];  // layer0 outputs [t][b][64]
__device__ float g_bufB[(size_t)TT * BB * HHH];  // layer1 outputs [t][b][64]
__device__ float g_hlast[BB * HHH];              // layer2 final h

// ---- f32x2 packed helpers ----
__device__ __forceinline__ void upk2(ull v, float& lo, float& hi) {
    asm("mov.b64 {%0, %1}, %2;" : "=f"(lo), "=f"(hi) : "l"(v));
}
__device__ __forceinline__ ull fma2(ull a, ull b, ull c) {
    ull d; asm("fma.rn.f32x2 %0, %1, %2, %3;" : "=l"(d) : "l"(a), "l"(b), "l"(c)); return d;
}
__device__ __forceinline__ ull add2(ull a, ull b) {
    ull d; asm("add.rn.f32x2 %0, %1, %2;" : "=l"(d) : "l"(a), "l"(b)); return d;
}
__device__ __forceinline__ float hsum2(ull v) {
    float lo, hi; upk2(v, lo, hi); return lo + hi;
}
__device__ __forceinline__ float fsigmoid(float x) {
    return __fdividef(1.0f, 1.0f + __expf(-x));
}
__device__ __forceinline__ float ftanhf(float x) {
    float e = __expf(2.0f * x);
    return 1.0f - __fdividef(2.0f, e + 1.0f);
}
__device__ __forceinline__ int P72(int k) { return k + 4 * (k >> 5); }

__device__ __forceinline__ void bar_sync_id(int id) {
    asm volatile("bar.sync %0, %1;" :: "r"(id), "r"(1024) : "memory");
}
__device__ __forceinline__ void bar_arrive_id(int id) {
    asm volatile("bar.arrive %0, %1;" :: "r"(id), "r"(1024) : "memory");
}

// ---------------------------------------------------------------------------
// Fused GRU layer with split-barrier software pipelining.
// 128 blocks x 512 threads; block owns batch rows [8*blk, 8*blk+8).
// Thread (tau=(lane&3)|(warp<<2), s=lane>>2): W_hh + W_ih slices in REGISTERS.
// Per step: sync(h ready) -> h-dot (2 passes x 4 rows) + shfl transpose-reduce
// -> update (h in register, thread owns (ROWN,tau)) -> out-store -> publish h
// -> stage x(t+2) -> arrive -> [slack region:] x-dot(t+1) + reduce, LDG x(t+3).
// Named barriers 1/2 alternate by step parity; count 1024 = 512 arr + 512 sync.
// x ring is 3-deep; STS pre-arrive so release/acquire orders it for readers.
// INW = 16 (layer0: x is [b][t][16]) or 64 (prev layer [t][b][64]).
// WALL = 1: write all timesteps; 0: only final h.
// ---------------------------------------------------------------------------
template <int INW, int WALL>
__global__ void __launch_bounds__(512, 1) gru_fused(
    const float* __restrict__ xin,
    const float* __restrict__ Wih, const float* __restrict__ Whh,
    const float* __restrict__ bih, const float* __restrict__ bhh,
    float* __restrict__ outbuf)
{
    constexpr int XSTR = (INW == 64) ? 72 : 18;
    __shared__ float hbuf[2][8 * 72];
    __shared__ float xsh[3][8 * XSTR];

    const int tid  = threadIdx.x;
    const int warp = tid >> 5;
    const int lane = tid & 31;
    const int tau  = (lane & 3) | (warp << 2);   // 0..63
    const int s    = lane >> 2;                  // 0..7
    const int sb0  = s & 1, sb1 = (s >> 1) & 1, sb2 = s >> 2;
    const int ROWN = 4 * sb2 + 2 * sb0 + sb1;    // owned (row) in update
    const int b0   = blockIdx.x * 8;
    const int hoff = 8 * s + 4 * (s >> 2);       // swizzled k offset

    // --- weights in registers ---
    ull wh[3][4];
#pragma unroll
    for (int g = 0; g < 3; g++)
#pragma unroll
        for (int kp = 0; kp < 4; kp++)
            wh[g][kp] = *(const ull*)(Whh + (size_t)(g * 64 + tau) * 64 + 8 * s + 2 * kp);

    constexpr int NXU = (INW == 64) ? 4 : 1;
    ull wx[3][NXU];
    if (INW == 64) {
#pragma unroll
        for (int g = 0; g < 3; g++)
#pragma unroll
            for (int kp = 0; kp < 4; kp++)
                wx[g][kp] = *(const ull*)(Wih + (size_t)(g * 64 + tau) * 64 + 8 * s + 2 * kp);
    } else {
#pragma unroll
        for (int g = 0; g < 3; g++)
            wx[g][0] = *(const ull*)(Wih + (size_t)(g * 64 + tau) * 16 + 2 * s);
    }

    const float bR  = __ldg(bih + tau)      + __ldg(bhh + tau);
    const float bZ  = __ldg(bih + 64 + tau) + __ldg(bhh + 64 + tau);
    const float bNx = __ldg(bih + 128 + tau);
    const float bNh = __ldg(bhh + 128 + tau);

    // x-dot over one staged slot -> reduced (xr,xz,xn) for (ROWN,tau)
    auto xdot = [&](const float* xb, float& oxr, float& oxz, float& oxn) {
#pragma unroll
        for (int p = 0; p < 2; p++) {
            ull aR[4], aZ[4], aN[4];
#pragma unroll
            for (int r = 0; r < 4; r++) { aR[r] = 0; aZ[r] = 0; aN[r] = 0; }
#pragma unroll
            for (int r = 0; r < 4; r++) {
                const int row = p * 4 + r;
                if (INW == 64) {
                    const ulonglong2* xq = (const ulonglong2*)(xb + row * 72 + hoff);
                    ulonglong2 C = xq[0], D = xq[1];
                    aR[r] = fma2(wx[0][0], C.x, aR[r]); aR[r] = fma2(wx[0][1], C.y, aR[r]);
                    aR[r] = fma2(wx[0][2], D.x, aR[r]); aR[r] = fma2(wx[0][3], D.y, aR[r]);
                    aZ[r] = fma2(wx[1][0], C.x, aZ[r]); aZ[r] = fma2(wx[1][1], C.y, aZ[r]);
                    aZ[r] = fma2(wx[1][2], D.x, aZ[r]); aZ[r] = fma2(wx[1][3], D.y, aZ[r]);
                    aN[r] = fma2(wx[2][0], C.x, aN[r]); aN[r] = fma2(wx[2][1], C.y, aN[r]);
                    aN[r] = fma2(wx[2][2], D.x, aN[r]); aN[r] = fma2(wx[2][3], D.y, aN[r]);
                } else {
                    ull xv = *(const ull*)(xb + row * 18 + 2 * s);
                    aR[r] = fma2(wx[0][0], xv, aR[r]);
                    aZ[r] = fma2(wx[1][0], xv, aZ[r]);
                    aN[r] = fma2(wx[2][0], xv, aN[r]);
                }
            }
#pragma unroll
            for (int pl = 0; pl < 3; pl++) {
                ull* a = (pl == 0) ? aR : (pl == 1) ? aZ : aN;
                ull s0v = sb0 ? a[0] : a[2];
                ull s1v = sb0 ? a[1] : a[3];
                ull r0v = __shfl_xor_sync(0xffffffffu, s0v, 4);
                ull r1v = __shfl_xor_sync(0xffffffffu, s1v, 4);
                ull b0v = add2(sb0 ? a[2] : a[0], r0v);
                ull b1v = add2(sb0 ? a[3] : a[1], r1v);
                ull s2v = sb1 ? b0v : b1v;
                ull r2v = __shfl_xor_sync(0xffffffffu, s2v, 8);
                ull cv  = add2(sb1 ? b1v : b0v, r2v);
                ull dv  = add2(cv, __shfl_xor_sync(0xffffffffu, cv, 16));
                if (p == sb2) {
                    float v = hsum2(dv);
                    if (pl == 0) oxr = v; else if (pl == 1) oxz = v; else oxn = v;
                }
            }
        }
    };

    // --- init: zero hbuf; stage x(0),x(1); prefetch x(2) ---
    for (int e = tid; e < 2 * 8 * 72; e += 512) ((float*)hbuf)[e] = 0.0f;

    const int orow = tid >> 6, ocol = tid & 63;   // INW64 staging role
    const int xrow = tid >> 4, xcol = tid & 15;   // INW16 staging role (tid<128)
    float xreg = 0.0f;
    if (INW == 64) {
        xsh[0][orow * 72 + P72(ocol)] = __ldg(xin + ((size_t)0 * BB + b0 + orow) * 64 + ocol);
        xsh[1][orow * 72 + P72(ocol)] = __ldg(xin + ((size_t)1 * BB + b0 + orow) * 64 + ocol);
        xreg = __ldg(xin + ((size_t)2 * BB + b0 + orow) * 64 + ocol);
    } else if (tid < 128) {
        xsh[0][xrow * 18 + xcol] = __ldg(xin + ((size_t)(b0 + xrow) * TT + 0) * 16 + xcol);
        xsh[1][xrow * 18 + xcol] = __ldg(xin + ((size_t)(b0 + xrow) * TT + 1) * 16 + xcol);
        xreg = __ldg(xin + ((size_t)(b0 + xrow) * TT + 2) * 16 + xcol);
    }
    __syncthreads();

    float h = 0.0f;
    float xr, xz, xn;
    xdot(xsh[0], xr, xz, xn);        // xacc for t=0
    bar_arrive_id(1);                // h(0) (zeros) published

    int snx = 1, sst = 2;            // read slot for t+1, store slot for t+2

#pragma unroll 1
    for (int t = 0; t < TT; ++t) {
        const int pc = t & 1;
        bar_sync_id(1 + pc);         // h(t) ready in hbuf[pc]
        const float* hb = hbuf[pc];

        // ---- h-dot + reduce ----
        float fr, fz, fnh;
#pragma unroll
        for (int p = 0; p < 2; p++) {
            ull aR[4], aZ[4], aNh[4];
#pragma unroll
            for (int r = 0; r < 4; r++) { aR[r] = 0; aZ[r] = 0; aNh[r] = 0; }
#pragma unroll
            for (int r = 0; r < 4; r++) {
                const int row = p * 4 + r;
                const ulonglong2* hq = (const ulonglong2*)(hb + row * 72 + hoff);
                ulonglong2 A = hq[0], B = hq[1];
                aR[r]  = fma2(wh[0][0], A.x, aR[r]);  aR[r]  = fma2(wh[0][1], A.y, aR[r]);
                aR[r]  = fma2(wh[0][2], B.x, aR[r]);  aR[r]  = fma2(wh[0][3], B.y, aR[r]);
                aZ[r]  = fma2(wh[1][0], A.x, aZ[r]);  aZ[r]  = fma2(wh[1][1], A.y, aZ[r]);
                aZ[r]  = fma2(wh[1][2], B.x, aZ[r]);  aZ[r]  = fma2(wh[1][3], B.y, aZ[r]);
                aNh[r] = fma2(wh[2][0], A.x, aNh[r]); aNh[r] = fma2(wh[2][1], A.y, aNh[r]);
                aNh[r] = fma2(wh[2][2], B.x, aNh[r]); aNh[r] = fma2(wh[2][3], B.y, aNh[r]);
            }
#pragma unroll
            for (int pl = 0; pl < 3; pl++) {
                ull* a = (pl == 0) ? aR : (pl == 1) ? aZ : aNh;
                ull s0v = sb0 ? a[0] : a[2];
                ull s1v = sb0 ? a[1] : a[3];
                ull r0v = __shfl_xor_sync(0xffffffffu, s0v, 4);
                ull r1v = __shfl_xor_sync(0xffffffffu, s1v, 4);
                ull b0v = add2(sb0 ? a[2] : a[0], r0v);
                ull b1v = add2(sb0 ? a[3] : a[1], r1v);
                ull s2v = sb1 ? b0v : b1v;
                ull r2v = __shfl_xor_sync(0xffffffffu, s2v, 8);
                ull cv  = add2(sb1 ? b1v : b0v, r2v);
                ull dv  = add2(cv, __shfl_xor_sync(0xffffffffu, cv, 16));
                if (p == sb2) {
                    float v = hsum2(dv);
                    if (pl == 0) fr = v; else if (pl == 1) fz = v; else fnh = v;
                }
            }
        }

        // ---- update (in-register h for (ROWN, tau)) ----
        float r = fsigmoid(xr + fr + bR);
        float z = fsigmoid(xz + fz + bZ);
        float n = ftanhf(xn + bNx + r * (fnh + bNh));
        h = fmaf(z, h - n, n);

        if (WALL) {
            outbuf[((size_t)t * BB + b0 + ROWN) * 64 + tau] = h;
        } else if (t == TT - 1) {
            outbuf[(size_t)(b0 + ROWN) * 64 + tau] = h;
        }
        hbuf[pc ^ 1][ROWN * 72 + P72(tau)] = h;

        // stage x(t+2) BEFORE arrive (release orders it for next step's readers)
        if (INW == 64) {
            xsh[sst][orow * 72 + P72(ocol)] = xreg;
        } else if (tid < 128) {
            xsh[sst][xrow * 18 + xcol] = xreg;
        }
        bar_arrive_id(1 + (pc ^ 1));   // h(t+1) published

        // ---- slack region: x-dot(t+1), prefetch x(t+3) ----
        xdot(xsh[snx], xr, xz, xn);
        const int t3 = (t + 3 < TT) ? t + 3 : TT - 1;
        if (INW == 64) {
            xreg = __ldg(xin + ((size_t)t3 * BB + b0 + orow) * 64 + ocol);
        } else if (tid < 128) {
            xreg = __ldg(xin + ((size_t)(b0 + xrow) * TT + t3) * 16 + xcol);
        }
        snx = (snx == 2) ? 0 : snx + 1;
        sst = (sst == 2) ? 0 : sst + 1;
    }
}

// ---------------------------------------------------------------------------
// Head: y[b] = fc2_b + fc2_w . relu(fc1_w @ h_last[b] + fc1_b)
// ---------------------------------------------------------------------------
__global__ void __launch_bounds__(256) head_kernel(
    const float* __restrict__ fc1w, const float* __restrict__ fc1b,
    const float* __restrict__ fc2w, const float* __restrict__ fc2b,
    float* __restrict__ y)
{
    __shared__ float s1[32 * 64];
    __shared__ float sb1[32];
    __shared__ float sw2[32];
    const int tid = threadIdx.x;
    for (int e = tid; e < 2048; e += 256) s1[e] = fc1w[e];
    if (tid < 32) { sb1[tid] = fc1b[tid]; sw2[tid] = fc2w[tid]; }
    __syncthreads();

    const int b = blockIdx.x * 256 + tid;
    const float* hp = g_hlast + (size_t)b * HHH;
    float hv[64];
#pragma unroll
    for (int q = 0; q < 16; q++) {
        float4 v = *(const float4*)(hp + q * 4);
        hv[q * 4] = v.x; hv[q * 4 + 1] = v.y; hv[q * 4 + 2] = v.z; hv[q * 4 + 3] = v.w;
    }
    float acc = __ldg(fc2b);
#pragma unroll
    for (int j = 0; j < 32; j++) {
        float sacc = sb1[j];
#pragma unroll
        for (int k = 0; k < 64; k++) sacc = fmaf(s1[j * 64 + k], hv[k], sacc);
        acc = fmaf(sw2[j], fmaxf(sacc, 0.0f), acc);
    }
    y[b] = acc;
}

// ---------------------------------------------------------------------------
extern "C" void kernel_launch(void* const* d_in, const int* in_sizes, int n_in,
                              void* d_out, int out_size)
{
    const float* x    = (const float*)d_in[0];
    const float* Wih0 = (const float*)d_in[1];
    const float* Whh0 = (const float*)d_in[2];
    const float* bih0 = (const float*)d_in[3];
    const float* bhh0 = (const float*)d_in[4];
    const float* Wih1 = (const float*)d_in[5];
    const float* Whh1 = (const float*)d_in[6];
    const float* bih1 = (const float*)d_in[7];
    const float* bhh1 = (const float*)d_in[8];
    const float* Wih2 = (const float*)d_in[9];
    const float* Whh2 = (const float*)d_in[10];
    const float* bih2 = (const float*)d_in[11];
    const float* bhh2 = (const float*)d_in[12];
    const float* fc1w = (const float*)d_in[13];
    const float* fc1b = (const float*)d_in[14];
    const float* fc2w = (const float*)d_in[15];
    const float* fc2b = (const float*)d_in[16];
    float* y = (float*)d_out;
    (void)in_sizes; (void)n_in; (void)out_size;

    float *bufA = nullptr, *bufB = nullptr, *hlast = nullptr;
    cudaGetSymbolAddress((void**)&bufA, g_bufA);
    cudaGetSymbolAddress((void**)&bufB, g_bufB);
    cudaGetSymbolAddress((void**)&hlast, g_hlast);

    gru_fused<16, 1><<<128, 512>>>(x,    Wih0, Whh0, bih0, bhh0, bufA);
    gru_fused<64, 1><<<128, 512>>>(bufA, Wih1, Whh1, bih1, bhh1, bufB);
    gru_fused<64, 0><<<128, 512>>>(bufB, Wih2, Whh2, bih2, bhh2, hlast);
    head_kernel<<<4, 256>>>(fc1w, fc1b, fc2w, fc2b, y);
}

// round 13
// speedup vs baseline: 2.2151x; 2.0107x over previous
#include <cuda_runtime.h>
#include <cuda_bf16.h>
#include <cstdint>

#define BB 1024
#define TT 512

// Scratch (device globals — allocation-free per harness rules)
__device__ float g_bufA[(size_t)TT * BB * 64];  // layer0 outputs [t][b][64]
__device__ float g_bufB[(size_t)TT * BB * 64];  // layer1 outputs [t][b][64]
__device__ float g_hlast[BB * 64];              // layer2 final h

__device__ __forceinline__ float fsigmoid(float x) {
    return __fdividef(1.0f, 1.0f + __expf(-x));
}
__device__ __forceinline__ float ftanhf(float x) {
    float e = __expf(2.0f * x);
    return 1.0f - __fdividef(2.0f, e + 1.0f);
}
__device__ __forceinline__ uint32_t smaddr(const void* p) {
    uint32_t a;
    asm("{ .reg .u64 t; cvta.to.shared.u64 t, %1; cvt.u32.u64 %0, t; }" : "=r"(a) : "l"(p));
    return a;
}
// split (v0,v1) into bf16 hi-pair and residual lo-pair (v0 in low half = lower col)
__device__ __forceinline__ void split2(float v0, float v1, uint32_t& hi, uint32_t& lo) {
    __nv_bfloat16 h0 = __float2bfloat16(v0), h1 = __float2bfloat16(v1);
    hi = ((uint32_t)__bfloat16_as_ushort(h1) << 16) | (uint32_t)__bfloat16_as_ushort(h0);
    __nv_bfloat16 g0 = __float2bfloat16(v0 - __bfloat162float(h0));
    __nv_bfloat16 g1 = __float2bfloat16(v1 - __bfloat162float(h1));
    lo = ((uint32_t)__bfloat16_as_ushort(g1) << 16) | (uint32_t)__bfloat16_as_ushort(g0);
}
__device__ __forceinline__ void mma16816(float c[4], const uint32_t a[4], const uint32_t b[2]) {
    asm volatile(
        "mma.sync.aligned.m16n8k16.row.col.f32.bf16.bf16.f32 "
        "{%0,%1,%2,%3}, {%4,%5,%6,%7}, {%8,%9}, {%0,%1,%2,%3};"
        : "+f"(c[0]), "+f"(c[1]), "+f"(c[2]), "+f"(c[3])
        : "r"(a[0]), "r"(a[1]), "r"(a[2]), "r"(a[3]), "r"(b[0]), "r"(b[1]));
}
#define LDMX4(R, ADDR) \
    asm volatile("ldmatrix.sync.aligned.m8n8.x4.shared.b16 {%0,%1,%2,%3}, [%4];" \
        : "=r"((R)[0]), "=r"((R)[1]), "=r"((R)[2]), "=r"((R)[3]) : "r"(ADDR))

// ---------------------------------------------------------------------------
// HMMA fused GRU layer. 128 blocks x 256 threads; block owns 8 batch rows.
// A(t) = [h(t-1) | x(t)]  (16 x KTOT bf16, rows 8-15 zero), hi/lo planes,
// ping-pong by step parity; B = [W_hh | W_ih] bf16 hi/lo fragments in REGS.
// Warp w owns gate-units [8w,8w+8): C tiles r/z/nh/nx accumulate over KS
// k-steps x 3 passes (hi*hi, hi*lo, lo*hi). Thread (lane) owns C elems
// (row = lane>>2, units u=8w+2(lane&3), u+1): applies GRU update with h in
// registers, publishes h(t)+x(t+1) into A[p^1]. ONE __syncthreads per step.
// INW = 16 (layer0: x is [b][t][16]) or 64 (prev layer [t][b][64]).
// WALL = 1: write all timesteps; 0: only final h.
// ---------------------------------------------------------------------------
template <int INW, int WALL>
__global__ void __launch_bounds__(256, 1) gru_hmma(
    const float* __restrict__ xin,
    const float* __restrict__ Wih, const float* __restrict__ Whh,
    const float* __restrict__ bih, const float* __restrict__ bhh,
    float* __restrict__ outbuf)
{
    constexpr int KTOT = 64 + INW;              // 128 or 80
    constexpr int KS   = KTOT / 16;             // 8 or 5
    constexpr int SW   = (INW == 64) ? 68 : 44; // A row stride in 32b words (pad: conflict-free)

    __shared__ uint32_t Asm[2][2][16 * SW];     // [parity][hi/lo][row*SW + word]

    const int tid  = threadIdx.x;
    const int warp = tid >> 5;
    const int lane = tid & 31;
    const int grp  = lane >> 2;        // row 0..7 (also gate-col group for B)
    const int qd   = lane & 3;
    const int u    = 8 * warp + 2 * qd;
    const int b0   = blockIdx.x * 8;

    // ---- B fragments (hi/lo) in registers, loaded once ----
    uint32_t bh[3][KS][2], bl[3][KS][2];
#pragma unroll
    for (int gi = 0; gi < 3; gi++) {
        const int g = gi * 64 + 8 * warp + grp;
#pragma unroll
        for (int ks = 0; ks < KS; ks++) {
            const float* src = (ks < 4) ? (Whh + (size_t)g * 64 + ks * 16)
                                        : (Wih + (size_t)g * INW + (ks - 4) * 16);
            const int kk = 2 * qd;
            float f0 = __ldg(src + kk),     f1 = __ldg(src + kk + 1);
            float f2 = __ldg(src + kk + 8), f3 = __ldg(src + kk + 9);
            split2(f0, f1, bh[gi][ks][0], bl[gi][ks][0]);
            split2(f2, f3, bh[gi][ks][1], bl[gi][ks][1]);
        }
    }

    // biases for owned units u, u+1
    const float bRv0 = __ldg(bih + u)       + __ldg(bhh + u);
    const float bRv1 = __ldg(bih + u + 1)   + __ldg(bhh + u + 1);
    const float bZv0 = __ldg(bih + 64 + u)  + __ldg(bhh + 64 + u);
    const float bZv1 = __ldg(bih + 65 + u)  + __ldg(bhh + 65 + u);
    const float bNx0 = __ldg(bih + 128 + u), bNx1 = __ldg(bih + 129 + u);
    const float bNh0 = __ldg(bhh + 128 + u), bNh1 = __ldg(bhh + 129 + u);

    // zero A (rows 8-15 stay zero forever; h(-1)=0)
    for (int e = tid; e < 2 * 2 * 16 * SW; e += 256) (&Asm[0][0][0])[e] = 0u;
    __syncthreads();

    // per-lane ldmatrix base addresses: lanes 0-7 rows0-7/m0, 8-15 rows8-15/m1,
    // 16-23 rows0-7 cols+8/m2, 24-31 rows8-15 cols+8/m3
    uint32_t ab[2][2];
#pragma unroll
    for (int pp = 0; pp < 2; pp++)
#pragma unroll
        for (int pl = 0; pl < 2; pl++)
            ab[pp][pl] = smaddr(&Asm[pp][pl][0]) + (lane & 15) * (SW * 4) + (lane >> 4) * 16;

    // stage x(0) into A[0]; xc = x(1)
    float xc0 = 0.0f, xc1 = 0.0f;
    if (INW == 64) {
        float2 v0 = *(const float2*)(xin + ((size_t)0 * BB + b0 + grp) * 64 + u);
        uint32_t hi, lo; split2(v0.x, v0.y, hi, lo);
        Asm[0][0][grp * SW + 32 + 4 * warp + qd] = hi;
        Asm[0][1][grp * SW + 32 + 4 * warp + qd] = lo;
        float2 v1 = *(const float2*)(xin + ((size_t)1 * BB + b0 + grp) * 64 + u);
        xc0 = v1.x; xc1 = v1.y;
    } else if (tid < 64) {
        const int xr = tid >> 3, xu = 2 * (tid & 7);
        float2 v0 = *(const float2*)(xin + ((size_t)(b0 + xr) * TT + 0) * 16 + xu);
        uint32_t hi, lo; split2(v0.x, v0.y, hi, lo);
        Asm[0][0][xr * SW + 32 + (tid & 7)] = hi;
        Asm[0][1][xr * SW + 32 + (tid & 7)] = lo;
        float2 v1 = *(const float2*)(xin + ((size_t)(b0 + xr) * TT + 1) * 16 + xu);
        xc0 = v1.x; xc1 = v1.y;
    }
    __syncthreads();

    float hv0 = 0.0f, hv1 = 0.0f;

#pragma unroll 1
    for (int t = 0; t < TT; ++t) {
        const int pp = t & 1;

        // prefetch x(t+2) (hidden under mma phase)
        float xn0 = 0.0f, xn1 = 0.0f;
        const int t2 = (t + 2 < TT) ? t + 2 : TT - 1;
        if (INW == 64) {
            float2 v = *(const float2*)(xin + ((size_t)t2 * BB + b0 + grp) * 64 + u);
            xn0 = v.x; xn1 = v.y;
        } else if (tid < 64) {
            const int xr = tid >> 3, xu = 2 * (tid & 7);
            float2 v = *(const float2*)(xin + ((size_t)(b0 + xr) * TT + t2) * 16 + xu);
            xn0 = v.x; xn1 = v.y;
        }

        // ---- mma phase: C = [h|x] @ [Whh|Wih]^T for warp's 8 units ----
        float cR[4]  = {0.f, 0.f, 0.f, 0.f};
        float cZ[4]  = {0.f, 0.f, 0.f, 0.f};
        float cNh[4] = {0.f, 0.f, 0.f, 0.f};
        float cNx[4] = {0.f, 0.f, 0.f, 0.f};
#pragma unroll
        for (int ks = 0; ks < KS; ks++) {
            uint32_t ah[4], al[4];
            LDMX4(ah, ab[pp][0] + ks * 32);
            LDMX4(al, ab[pp][1] + ks * 32);
            mma16816(cR, ah, bh[0][ks]);
            mma16816(cR, ah, bl[0][ks]);
            mma16816(cR, al, bh[0][ks]);
            mma16816(cZ, ah, bh[1][ks]);
            mma16816(cZ, ah, bl[1][ks]);
            mma16816(cZ, al, bh[1][ks]);
            float* cN = (ks < 4) ? cNh : cNx;   // n-gate: h-part vs x-part
            mma16816(cN, ah, bh[2][ks]);
            mma16816(cN, ah, bl[2][ks]);
            mma16816(cN, al, bh[2][ks]);
        }

        // ---- update: thread owns (row grp, units u, u+1); h in registers ----
        float r0 = fsigmoid(cR[0] + bRv0), r1 = fsigmoid(cR[1] + bRv1);
        float z0 = fsigmoid(cZ[0] + bZv0), z1 = fsigmoid(cZ[1] + bZv1);
        float n0 = ftanhf(cNx[0] + bNx0 + r0 * (cNh[0] + bNh0));
        float n1 = ftanhf(cNx[1] + bNx1 + r1 * (cNh[1] + bNh1));
        hv0 = n0 + z0 * (hv0 - n0);
        hv1 = n1 + z1 * (hv1 - n1);

        if (WALL) {
            float2 st; st.x = hv0; st.y = hv1;
            *(float2*)(outbuf + ((size_t)t * BB + b0 + grp) * 64 + u) = st;
        }

        // publish h(t) and x(t+1) into A[pp^1]
        {
            uint32_t hi, lo; split2(hv0, hv1, hi, lo);
            Asm[pp ^ 1][0][grp * SW + 4 * warp + qd] = hi;
            Asm[pp ^ 1][1][grp * SW + 4 * warp + qd] = lo;
        }
        if (INW == 64) {
            uint32_t hi, lo; split2(xc0, xc1, hi, lo);
            Asm[pp ^ 1][0][grp * SW + 32 + 4 * warp + qd] = hi;
            Asm[pp ^ 1][1][grp * SW + 32 + 4 * warp + qd] = lo;
        } else if (tid < 64) {
            uint32_t hi, lo; split2(xc0, xc1, hi, lo);
            const int xr = tid >> 3;
            Asm[pp ^ 1][0][xr * SW + 32 + (tid & 7)] = hi;
            Asm[pp ^ 1][1][xr * SW + 32 + (tid & 7)] = lo;
        }
        xc0 = xn0; xc1 = xn1;
        __syncthreads();
    }

    if (!WALL) {
        float2 st; st.x = hv0; st.y = hv1;
        *(float2*)(outbuf + (size_t)(b0 + grp) * 64 + u) = st;
    }
}

// ---------------------------------------------------------------------------
// Head: y[b] = fc2_b + fc2_w . relu(fc1_w @ h_last[b] + fc1_b)
// ---------------------------------------------------------------------------
__global__ void __launch_bounds__(256) head_kernel(
    const float* __restrict__ fc1w, const float* __restrict__ fc1b,
    const float* __restrict__ fc2w, const float* __restrict__ fc2b,
    float* __restrict__ y)
{
    __shared__ float s1[32 * 64];
    __shared__ float sb1[32];
    __shared__ float sw2[32];
    const int tid = threadIdx.x;
    for (int e = tid; e < 2048; e += 256) s1[e] = fc1w[e];
    if (tid < 32) { sb1[tid] = fc1b[tid]; sw2[tid] = fc2w[tid]; }
    __syncthreads();

    const int b = blockIdx.x * 256 + tid;
    const float* hp = g_hlast + (size_t)b * 64;
    float hv[64];
#pragma unroll
    for (int q = 0; q < 16; q++) {
        float4 v = *(const float4*)(hp + q * 4);
        hv[q * 4] = v.x; hv[q * 4 + 1] = v.y; hv[q * 4 + 2] = v.z; hv[q * 4 + 3] = v.w;
    }
    float acc = __ldg(fc2b);
#pragma unroll
    for (int j = 0; j < 32; j++) {
        float sacc = sb1[j];
#pragma unroll
        for (int k = 0; k < 64; k++) sacc = fmaf(s1[j * 64 + k], hv[k], sacc);
        acc = fmaf(sw2[j], fmaxf(sacc, 0.0f), acc);
    }
    y[b] = acc;
}

// ---------------------------------------------------------------------------
extern "C" void kernel_launch(void* const* d_in, const int* in_sizes, int n_in,
                              void* d_out, int out_size)
{
    const float* x    = (const float*)d_in[0];
    const float* Wih0 = (const float*)d_in[1];
    const float* Whh0 = (const float*)d_in[2];
    const float* bih0 = (const float*)d_in[3];
    const float* bhh0 = (const float*)d_in[4];
    const float* Wih1 = (const float*)d_in[5];
    const float* Whh1 = (const float*)d_in[6];
    const float* bih1 = (const float*)d_in[7];
    const float* bhh1 = (const float*)d_in[8];
    const float* Wih2 = (const float*)d_in[9];
    const float* Whh2 = (const float*)d_in[10];
    const float* bih2 = (const float*)d_in[11];
    const float* bhh2 = (const float*)d_in[12];
    const float* fc1w = (const float*)d_in[13];
    const float* fc1b = (const float*)d_in[14];
    const float* fc2w = (const float*)d_in[15];
    const float* fc2b = (const float*)d_in[16];
    float* y = (float*)d_out;
    (void)in_sizes; (void)n_in; (void)out_size;

    float *bufA = nullptr, *bufB = nullptr, *hlast = nullptr;
    cudaGetSymbolAddress((void**)&bufA, g_bufA);
    cudaGetSymbolAddress((void**)&bufB, g_bufB);
    cudaGetSymbolAddress((void**)&hlast, g_hlast);

    gru_hmma<16, 1><<<128, 256>>>(x,    Wih0, Whh0, bih0, bhh0, bufA);
    gru_hmma<64, 1><<<128, 256>>>(bufA, Wih1, Whh1, bih1, bhh1, bufB);
    gru_hmma<64, 0><<<128, 256>>>(bufB, Wih2, Whh2, bih2, bhh2, hlast);
    head_kernel<<<4, 256>>>(fc1w, fc1b, fc2w, fc2b, y);
}

// round 14
// speedup vs baseline: 2.9395x; 1.3270x over previous
#include <cuda_runtime.h>
#include <cuda_fp16.h>
#include <cstdint>

#define BB 1024
#define TT 512

// Scratch (device globals — allocation-free per harness rules)
__device__ float g_bufA[(size_t)TT * BB * 64];  // layer0 outputs [t][b][64]
__device__ float g_bufB[(size_t)TT * BB * 64];  // layer1 outputs [t][b][64]
__device__ float g_hlast[BB * 64];              // layer2 final h

__device__ __forceinline__ float fsigmoid(float x) {
    return __fdividef(1.0f, 1.0f + __expf(-x));
}
__device__ __forceinline__ float ftanhf(float x) {
    float e = __expf(2.0f * x);
    return 1.0f - __fdividef(2.0f, e + 1.0f);
}
__device__ __forceinline__ uint32_t smaddr(const void* p) {
    uint32_t a;
    asm("{ .reg .u64 t; cvta.to.shared.u64 t, %1; cvt.u32.u64 %0, t; }" : "=r"(a) : "l"(p));
    return a;
}
// A-split: (v0,v1) -> fp16 hi-pair + fp16 residual lo-pair (a = hi+lo exact to ~2^-22)
__device__ __forceinline__ void split2(float v0, float v1, uint32_t& hi, uint32_t& lo) {
    __half h0 = __float2half_rn(v0), h1 = __float2half_rn(v1);
    hi = ((uint32_t)__half_as_ushort(h1) << 16) | (uint32_t)__half_as_ushort(h0);
    __half g0 = __float2half_rn(v0 - __half2float(h0));
    __half g1 = __float2half_rn(v1 - __half2float(h1));
    lo = ((uint32_t)__half_as_ushort(g1) << 16) | (uint32_t)__half_as_ushort(g0);
}
// B-pack: fp16 single plane
__device__ __forceinline__ uint32_t packh(float v0, float v1) {
    __half h0 = __float2half_rn(v0), h1 = __float2half_rn(v1);
    return ((uint32_t)__half_as_ushort(h1) << 16) | (uint32_t)__half_as_ushort(h0);
}
__device__ __forceinline__ void mma16816(float c[4], const uint32_t a[4], const uint32_t b[2]) {
    asm volatile(
        "mma.sync.aligned.m16n8k16.row.col.f32.f16.f16.f32 "
        "{%0,%1,%2,%3}, {%4,%5,%6,%7}, {%8,%9}, {%0,%1,%2,%3};"
        : "+f"(c[0]), "+f"(c[1]), "+f"(c[2]), "+f"(c[3])
        : "r"(a[0]), "r"(a[1]), "r"(a[2]), "r"(a[3]), "r"(b[0]), "r"(b[1]));
}
#define LDMX4(R, ADDR) \
    asm volatile("ldmatrix.sync.aligned.m8n8.x4.shared.b16 {%0,%1,%2,%3}, [%4];" \
        : "=r"((R)[0]), "=r"((R)[1]), "=r"((R)[2]), "=r"((R)[3]) : "r"(ADDR))

// ---------------------------------------------------------------------------
// HMMA fused GRU layer, fp16 2-pass split.
// 128 blocks x 256 threads; block owns 8 batch rows.
// A(t) = [h(t-1) | x(t)] (16 x KTOT fp16, rows 8-15 zero) split hi/lo planes,
// ping-pong by step parity; B = [W_hh | W_ih] fp16 single plane in REGISTERS.
// Per kstep per gate: 2 mma ((ah+al)*bh). Warp w owns gate-units [8w,8w+8);
// thread (lane) owns C elems (row = lane>>2, units u=8w+2(lane&3), u+1);
// GRU update in-thread with h in registers; ONE __syncthreads per step.
// INW = 16 (layer0: x is [b][t][16]) or 64 (prev layer [t][b][64]).
// WALL = 1: write all timesteps; 0: only final h.
// ---------------------------------------------------------------------------
template <int INW, int WALL>
__global__ void __launch_bounds__(256, 1) gru_hmma(
    const float* __restrict__ xin,
    const float* __restrict__ Wih, const float* __restrict__ Whh,
    const float* __restrict__ bih, const float* __restrict__ bhh,
    float* __restrict__ outbuf)
{
    constexpr int KTOT = 64 + INW;              // 128 or 80
    constexpr int KS   = KTOT / 16;             // 8 or 5
    constexpr int SW   = (INW == 64) ? 68 : 44; // A row stride in 32b words

    __shared__ uint32_t Asm[2][2][16 * SW];     // [parity][hi/lo][row*SW + word]

    const int tid  = threadIdx.x;
    const int warp = tid >> 5;
    const int lane = tid & 31;
    const int grp  = lane >> 2;        // row 0..7 (also gate-col group for B)
    const int qd   = lane & 3;
    const int u    = 8 * warp + 2 * qd;
    const int b0   = blockIdx.x * 8;

    // ---- B fragments (fp16 hi only) in registers, loaded once ----
    uint32_t bh[3][KS][2];
#pragma unroll
    for (int gi = 0; gi < 3; gi++) {
        const int g = gi * 64 + 8 * warp + grp;
#pragma unroll
        for (int ks = 0; ks < KS; ks++) {
            const float* src = (ks < 4) ? (Whh + (size_t)g * 64 + ks * 16)
                                        : (Wih + (size_t)g * INW + (ks - 4) * 16);
            const int kk = 2 * qd;
            bh[gi][ks][0] = packh(__ldg(src + kk),     __ldg(src + kk + 1));
            bh[gi][ks][1] = packh(__ldg(src + kk + 8), __ldg(src + kk + 9));
        }
    }

    // biases for owned units u, u+1
    const float bRv0 = __ldg(bih + u)       + __ldg(bhh + u);
    const float bRv1 = __ldg(bih + u + 1)   + __ldg(bhh + u + 1);
    const float bZv0 = __ldg(bih + 64 + u)  + __ldg(bhh + 64 + u);
    const float bZv1 = __ldg(bih + 65 + u)  + __ldg(bhh + 65 + u);
    const float bNx0 = __ldg(bih + 128 + u), bNx1 = __ldg(bih + 129 + u);
    const float bNh0 = __ldg(bhh + 128 + u), bNh1 = __ldg(bhh + 129 + u);

    // zero A (rows 8-15 stay zero forever; h(-1)=0)
    for (int e = tid; e < 2 * 2 * 16 * SW; e += 256) (&Asm[0][0][0])[e] = 0u;
    __syncthreads();

    // per-lane ldmatrix base addresses
    uint32_t ab[2][2];
#pragma unroll
    for (int pp = 0; pp < 2; pp++)
#pragma unroll
        for (int pl = 0; pl < 2; pl++)
            ab[pp][pl] = smaddr(&Asm[pp][pl][0]) + (lane & 15) * (SW * 4) + (lane >> 4) * 16;

    // stage x(0) into A[0]; xc = x(1)
    float xc0 = 0.0f, xc1 = 0.0f;
    if (INW == 64) {
        float2 v0 = *(const float2*)(xin + ((size_t)0 * BB + b0 + grp) * 64 + u);
        uint32_t hi, lo; split2(v0.x, v0.y, hi, lo);
        Asm[0][0][grp * SW + 32 + 4 * warp + qd] = hi;
        Asm[0][1][grp * SW + 32 + 4 * warp + qd] = lo;
        float2 v1 = *(const float2*)(xin + ((size_t)1 * BB + b0 + grp) * 64 + u);
        xc0 = v1.x; xc1 = v1.y;
    } else if (tid < 64) {
        const int xr = tid >> 3, xu = 2 * (tid & 7);
        float2 v0 = *(const float2*)(xin + ((size_t)(b0 + xr) * TT + 0) * 16 + xu);
        uint32_t hi, lo; split2(v0.x, v0.y, hi, lo);
        Asm[0][0][xr * SW + 32 + (tid & 7)] = hi;
        Asm[0][1][xr * SW + 32 + (tid & 7)] = lo;
        float2 v1 = *(const float2*)(xin + ((size_t)(b0 + xr) * TT + 1) * 16 + xu);
        xc0 = v1.x; xc1 = v1.y;
    }
    __syncthreads();

    float hv0 = 0.0f, hv1 = 0.0f;

#pragma unroll 1
    for (int t = 0; t < TT; ++t) {
        const int pp = t & 1;

        // prefetch x(t+2) (hidden under mma phase)
        float xn0 = 0.0f, xn1 = 0.0f;
        const int t2 = (t + 2 < TT) ? t + 2 : TT - 1;
        if (INW == 64) {
            float2 v = *(const float2*)(xin + ((size_t)t2 * BB + b0 + grp) * 64 + u);
            xn0 = v.x; xn1 = v.y;
        } else if (tid < 64) {
            const int xr = tid >> 3, xu = 2 * (tid & 7);
            float2 v = *(const float2*)(xin + ((size_t)(b0 + xr) * TT + t2) * 16 + xu);
            xn0 = v.x; xn1 = v.y;
        }

        // ---- mma phase: C = [h|x] @ [Whh|Wih]^T, 2-pass fp16 ----
        float cR[4]  = {0.f, 0.f, 0.f, 0.f};
        float cZ[4]  = {0.f, 0.f, 0.f, 0.f};
        float cNh[4] = {0.f, 0.f, 0.f, 0.f};
        float cNx[4] = {0.f, 0.f, 0.f, 0.f};
#pragma unroll
        for (int ks = 0; ks < KS; ks++) {
            uint32_t ah[4], al[4];
            LDMX4(ah, ab[pp][0] + ks * 32);
            LDMX4(al, ab[pp][1] + ks * 32);
            mma16816(cR, ah, bh[0][ks]);
            mma16816(cR, al, bh[0][ks]);
            mma16816(cZ, ah, bh[1][ks]);
            mma16816(cZ, al, bh[1][ks]);
            float* cN = (ks < 4) ? cNh : cNx;   // n-gate: h-part vs x-part
            mma16816(cN, ah, bh[2][ks]);
            mma16816(cN, al, bh[2][ks]);
        }

        // ---- update: thread owns (row grp, units u, u+1); h in registers ----
        float r0 = fsigmoid(cR[0] + bRv0), r1 = fsigmoid(cR[1] + bRv1);
        float z0 = fsigmoid(cZ[0] + bZv0), z1 = fsigmoid(cZ[1] + bZv1);
        float n0 = ftanhf(cNx[0] + bNx0 + r0 * (cNh[0] + bNh0));
        float n1 = ftanhf(cNx[1] + bNx1 + r1 * (cNh[1] + bNh1));
        hv0 = n0 + z0 * (hv0 - n0);
        hv1 = n1 + z1 * (hv1 - n1);

        if (WALL) {
            float2 st; st.x = hv0; st.y = hv1;
            *(float2*)(outbuf + ((size_t)t * BB + b0 + grp) * 64 + u) = st;
        }

        // publish h(t) and x(t+1) into A[pp^1]
        {
            uint32_t hi, lo; split2(hv0, hv1, hi, lo);
            Asm[pp ^ 1][0][grp * SW + 4 * warp + qd] = hi;
            Asm[pp ^ 1][1][grp * SW + 4 * warp + qd] = lo;
        }
        if (INW == 64) {
            uint32_t hi, lo; split2(xc0, xc1, hi, lo);
            Asm[pp ^ 1][0][grp * SW + 32 + 4 * warp + qd] = hi;
            Asm[pp ^ 1][1][grp * SW + 32 + 4 * warp + qd] = lo;
        } else if (tid < 64) {
            uint32_t hi, lo; split2(xc0, xc1, hi, lo);
            const int xr = tid >> 3;
            Asm[pp ^ 1][0][xr * SW + 32 + (tid & 7)] = hi;
            Asm[pp ^ 1][1][xr * SW + 32 + (tid & 7)] = lo;
        }
        xc0 = xn0; xc1 = xn1;
        __syncthreads();
    }

    if (!WALL) {
        float2 st; st.x = hv0; st.y = hv1;
        *(float2*)(outbuf + (size_t)(b0 + grp) * 64 + u) = st;
    }
}

// ---------------------------------------------------------------------------
// Head: y[b] = fc2_b + fc2_w . relu(fc1_w @ h_last[b] + fc1_b)
// ---------------------------------------------------------------------------
__global__ void __launch_bounds__(256) head_kernel(
    const float* __restrict__ fc1w, const float* __restrict__ fc1b,
    const float* __restrict__ fc2w, const float* __restrict__ fc2b,
    float* __restrict__ y)
{
    __shared__ float s1[32 * 64];
    __shared__ float sb1[32];
    __shared__ float sw2[32];
    const int tid = threadIdx.x;
    for (int e = tid; e < 2048; e += 256) s1[e] = fc1w[e];
    if (tid < 32) { sb1[tid] = fc1b[tid]; sw2[tid] = fc2w[tid]; }
    __syncthreads();

    const int b = blockIdx.x * 256 + tid;
    const float* hp = g_hlast + (size_t)b * 64;
    float hv[64];
#pragma unroll
    for (int q = 0; q < 16; q++) {
        float4 v = *(const float4*)(hp + q * 4);
        hv[q * 4] = v.x; hv[q * 4 + 1] = v.y; hv[q * 4 + 2] = v.z; hv[q * 4 + 3] = v.w;
    }
    float acc = __ldg(fc2b);
#pragma unroll
    for (int j = 0; j < 32; j++) {
        float sacc = sb1[j];
#pragma unroll
        for (int k = 0; k < 64; k++) sacc = fmaf(s1[j * 64 + k], hv[k], sacc);
        acc = fmaf(sw2[j], fmaxf(sacc, 0.0f), acc);
    }
    y[b] = acc;
}

// ---------------------------------------------------------------------------
extern "C" void kernel_launch(void* const* d_in, const int* in_sizes, int n_in,
                              void* d_out, int out_size)
{
    const float* x    = (const float*)d_in[0];
    const float* Wih0 = (const float*)d_in[1];
    const float* Whh0 = (const float*)d_in[2];
    const float* bih0 = (const float*)d_in[3];
    const float* bhh0 = (const float*)d_in[4];
    const float* Wih1 = (const float*)d_in[5];
    const float* Whh1 = (const float*)d_in[6];
    const float* bih1 = (const float*)d_in[7];
    const float* bhh1 = (const float*)d_in[8];
    const float* Wih2 = (const float*)d_in[9];
    const float* Whh2 = (const float*)d_in[10];
    const float* bih2 = (const float*)d_in[11];
    const float* bhh2 = (const float*)d_in[12];
    const float* fc1w = (const float*)d_in[13];
    const float* fc1b = (const float*)d_in[14];
    const float* fc2w = (const float*)d_in[15];
    const float* fc2b = (const float*)d_in[16];
    float* y = (float*)d_out;
    (void)in_sizes; (void)n_in; (void)out_size;

    float *bufA = nullptr, *bufB = nullptr, *hlast = nullptr;
    cudaGetSymbolAddress((void**)&bufA, g_bufA);
    cudaGetSymbolAddress((void**)&bufB, g_bufB);
    cudaGetSymbolAddress((void**)&hlast, g_hlast);

    gru_hmma<16, 1><<<128, 256>>>(x,    Wih0, Whh0, bih0, bhh0, bufA);
    gru_hmma<64, 1><<<128, 256>>>(bufA, Wih1, Whh1, bih1, bhh1, bufB);
    gru_hmma<64, 0><<<128, 256>>>(bufB, Wih2, Whh2, bih2, bhh2, hlast);
    head_kernel<<<4, 256>>>(fc1w, fc1b, fc2w, fc2b, y);
}

// round 15
// speedup vs baseline: 2.9649x; 1.0086x over previous
#include <cuda_runtime.h>
#include <cuda_fp16.h>
#include <cstdint>

#define BB 1024
#define TT 512

// Scratch (device globals — allocation-free per harness rules)
__device__ float g_bufA[(size_t)TT * BB * 64];  // layer0 outputs [t][b][64]
__device__ float g_bufB[(size_t)TT * BB * 64];  // layer1 outputs [t][b][64]
__device__ float g_hlast[BB * 64];              // layer2 final h

__device__ __forceinline__ float fsigmoid(float x) {
    return __fdividef(1.0f, 1.0f + __expf(-x));
}
__device__ __forceinline__ float ftanhf(float x) {
    float e = __expf(2.0f * x);
    return 1.0f - __fdividef(2.0f, e + 1.0f);
}
__device__ __forceinline__ uint32_t smaddr(const void* p) {
    uint32_t a;
    asm("{ .reg .u64 t; cvta.to.shared.u64 t, %1; cvt.u32.u64 %0, t; }" : "=r"(a) : "l"(p));
    return a;
}
// split (v0,v1) -> fp16 hi-pair + fp16 residual lo-pair (hi+lo exact to ~2^-22)
__device__ __forceinline__ void split2(float v0, float v1, uint32_t& hi, uint32_t& lo) {
    __half h0 = __float2half_rn(v0), h1 = __float2half_rn(v1);
    hi = ((uint32_t)__half_as_ushort(h1) << 16) | (uint32_t)__half_as_ushort(h0);
    __half g0 = __float2half_rn(v0 - __half2float(h0));
    __half g1 = __float2half_rn(v1 - __half2float(h1));
    lo = ((uint32_t)__half_as_ushort(g1) << 16) | (uint32_t)__half_as_ushort(g0);
}
__device__ __forceinline__ uint32_t packh(float v0, float v1) {
    __half h0 = __float2half_rn(v0), h1 = __float2half_rn(v1);
    return ((uint32_t)__half_as_ushort(h1) << 16) | (uint32_t)__half_as_ushort(h0);
}
__device__ __forceinline__ void mma16816(float c[4], const uint32_t a[4], const uint32_t b[2]) {
    asm volatile(
        "mma.sync.aligned.m16n8k16.row.col.f32.f16.f16.f32 "
        "{%0,%1,%2,%3}, {%4,%5,%6,%7}, {%8,%9}, {%0,%1,%2,%3};"
        : "+f"(c[0]), "+f"(c[1]), "+f"(c[2]), "+f"(c[3])
        : "r"(a[0]), "r"(a[1]), "r"(a[2]), "r"(a[3]), "r"(b[0]), "r"(b[1]));
}
#define LDMX4(R, ADDR) \
    asm volatile("ldmatrix.sync.aligned.m8n8.x4.shared.b16 {%0,%1,%2,%3}, [%4];" \
        : "=r"((R)[0]), "=r"((R)[1]), "=r"((R)[2]), "=r"((R)[3]) : "r"(ADDR))

// ---------------------------------------------------------------------------
// HMMA fused GRU, fp16 2-pass, x-mma software-pipelined off the critical path.
// 128 blocks x 256 threads; block owns 8 batch rows (M rows 0-7 of 16).
// h ping-pong: Hsm[2][2][16*36]   (parity, hi/lo plane; stride 36 words)
// x ring     : Xsm[2][2][16*SWX]  (2-deep slot ring, decoupled from parity)
// Step t: sync -> h-mma (24) -> combine with xacc(t) (computed in step t-1)
// -> update (h in regs) -> publish h(t) -> stage x(t+2) -> x-mma(t+1) -> loop.
// INW = 16 (layer0: x is [b][t][16]) or 64 (prev layer [t][b][64]).
// WALL = 1: write all timesteps; 0: only final h.
// ---------------------------------------------------------------------------
template <int INW, int WALL>
__global__ void __launch_bounds__(256, 1) gru_hmma(
    const float* __restrict__ xin,
    const float* __restrict__ Wih, const float* __restrict__ Whh,
    const float* __restrict__ bih, const float* __restrict__ bhh,
    float* __restrict__ outbuf)
{
    constexpr int KSX = INW / 16;               // x k-steps: 4 or 1
    constexpr int SWH = 36;                     // h row stride (words): conflict-free
    constexpr int SWX = (INW == 64) ? 36 : 12;  // x row stride (words)

    __shared__ uint32_t Hsm[2][2][16 * SWH];
    __shared__ uint32_t Xsm[2][2][16 * SWX];

    const int tid  = threadIdx.x;
    const int warp = tid >> 5;
    const int lane = tid & 31;
    const int grp  = lane >> 2;        // row 0..7 (also gate-col group for B)
    const int qd   = lane & 3;
    const int u    = 8 * warp + 2 * qd;
    const int b0   = blockIdx.x * 8;

    // ---- B fragments (fp16) in registers: h-part (4 ksteps) + x-part ----
    uint32_t bhh_f[3][4][2], bhx_f[3][KSX][2];
#pragma unroll
    for (int gi = 0; gi < 3; gi++) {
        const int g = gi * 64 + 8 * warp + grp;
        const int kk = 2 * qd;
#pragma unroll
        for (int ks = 0; ks < 4; ks++) {
            const float* src = Whh + (size_t)g * 64 + ks * 16;
            bhh_f[gi][ks][0] = packh(__ldg(src + kk),     __ldg(src + kk + 1));
            bhh_f[gi][ks][1] = packh(__ldg(src + kk + 8), __ldg(src + kk + 9));
        }
#pragma unroll
        for (int ks = 0; ks < KSX; ks++) {
            const float* src = Wih + (size_t)g * INW + ks * 16;
            bhx_f[gi][ks][0] = packh(__ldg(src + kk),     __ldg(src + kk + 1));
            bhx_f[gi][ks][1] = packh(__ldg(src + kk + 8), __ldg(src + kk + 9));
        }
    }

    // biases for owned units u, u+1
    const float bRv0 = __ldg(bih + u)       + __ldg(bhh + u);
    const float bRv1 = __ldg(bih + u + 1)   + __ldg(bhh + u + 1);
    const float bZv0 = __ldg(bih + 64 + u)  + __ldg(bhh + 64 + u);
    const float bZv1 = __ldg(bih + 65 + u)  + __ldg(bhh + 65 + u);
    const float bNx0 = __ldg(bih + 128 + u), bNx1 = __ldg(bih + 129 + u);
    const float bNh0 = __ldg(bhh + 128 + u), bNh1 = __ldg(bhh + 129 + u);

    // zero H (both parities/planes; rows 8-15 stay zero) and X ring
    for (int e = tid; e < 2 * 2 * 16 * SWH; e += 256) (&Hsm[0][0][0])[e] = 0u;
    for (int e = tid; e < 2 * 2 * 16 * SWX; e += 256) (&Xsm[0][0][0])[e] = 0u;

    // ldmatrix per-lane addresses
    uint32_t hab[2][2], xab[2][2];
#pragma unroll
    for (int pp = 0; pp < 2; pp++)
#pragma unroll
        for (int pl = 0; pl < 2; pl++) {
            hab[pp][pl] = smaddr(&Hsm[pp][pl][0]) + (lane & 15) * (SWH * 4) + (lane >> 4) * 16;
            xab[pp][pl] = smaddr(&Xsm[pp][pl][0]) + (lane & 15) * (SWX * 4) + (lane >> 4) * 16;
        }
    __syncthreads();

    // ---- stage x(0)->slot0, x(1)->slot1; prefetch x(2) ----
    float xc0 = 0.0f, xc1 = 0.0f;   // x(t+2) register carry
    if (INW == 64) {
#pragma unroll
        for (int sl = 0; sl < 2; sl++) {
            float2 v = *(const float2*)(xin + ((size_t)sl * BB + b0 + grp) * 64 + u);
            uint32_t hi, lo; split2(v.x, v.y, hi, lo);
            Xsm[sl][0][grp * SWX + 4 * warp + qd] = hi;
            Xsm[sl][1][grp * SWX + 4 * warp + qd] = lo;
        }
        float2 v = *(const float2*)(xin + ((size_t)2 * BB + b0 + grp) * 64 + u);
        xc0 = v.x; xc1 = v.y;
    } else if (tid < 64) {
        const int xr = tid >> 3, xw = tid & 7;
#pragma unroll
        for (int sl = 0; sl < 2; sl++) {
            float2 v = *(const float2*)(xin + ((size_t)(b0 + xr) * TT + sl) * 16 + 2 * xw);
            uint32_t hi, lo; split2(v.x, v.y, hi, lo);
            Xsm[sl][0][xr * SWX + xw] = hi;
            Xsm[sl][1][xr * SWX + xw] = lo;
        }
        float2 v = *(const float2*)(xin + ((size_t)(b0 + xr) * TT + 2) * 16 + 2 * xw);
        xc0 = v.x; xc1 = v.y;
    }
    __syncthreads();

    // x-mma over one ring slot -> accumulators
    auto xmma = [&](int slot, float xR[4], float xZ[4], float xN[4]) {
#pragma unroll
        for (int ks = 0; ks < KSX; ks++) {
            uint32_t ah[4], al[4];
            LDMX4(ah, xab[slot][0] + ks * 32);
            LDMX4(al, xab[slot][1] + ks * 32);
            mma16816(xR, ah, bhx_f[0][ks]);
            mma16816(xR, al, bhx_f[0][ks]);
            mma16816(xZ, ah, bhx_f[1][ks]);
            mma16816(xZ, al, bhx_f[1][ks]);
            mma16816(xN, ah, bhx_f[2][ks]);
            mma16816(xN, al, bhx_f[2][ks]);
        }
    };

    float xR[4] = {0,0,0,0}, xZ[4] = {0,0,0,0}, xN[4] = {0,0,0,0};
    xmma(0, xR, xZ, xN);               // xacc for t=0

    float hv0 = 0.0f, hv1 = 0.0f;

#pragma unroll 1
    for (int t = 0; t < TT; ++t) {
        const int pp = t & 1;

        // ---- h-mma (critical path): 24 mma ----
        float cR[4]  = {xR[0], xR[1], xR[2], xR[3]};
        float cZ[4]  = {xZ[0], xZ[1], xZ[2], xZ[3]};
        float cNh[4] = {0.f, 0.f, 0.f, 0.f};
#pragma unroll
        for (int ks = 0; ks < 4; ks++) {
            uint32_t ah[4], al[4];
            LDMX4(ah, hab[pp][0] + ks * 32);
            LDMX4(al, hab[pp][1] + ks * 32);
            mma16816(cR, ah, bhh_f[0][ks]);
            mma16816(cR, al, bhh_f[0][ks]);
            mma16816(cZ, ah, bhh_f[1][ks]);
            mma16816(cZ, al, bhh_f[1][ks]);
            mma16816(cNh, ah, bhh_f[2][ks]);
            mma16816(cNh, al, bhh_f[2][ks]);
        }

        // ---- update: thread owns (row grp, units u,u+1); h in registers ----
        float r0 = fsigmoid(cR[0] + bRv0), r1 = fsigmoid(cR[1] + bRv1);
        float z0 = fsigmoid(cZ[0] + bZv0), z1 = fsigmoid(cZ[1] + bZv1);
        float n0 = ftanhf(xN[0] + bNx0 + r0 * (cNh[0] + bNh0));
        float n1 = ftanhf(xN[1] + bNx1 + r1 * (cNh[1] + bNh1));
        hv0 = n0 + z0 * (hv0 - n0);
        hv1 = n1 + z1 * (hv1 - n1);

        if (WALL) {
            float2 st; st.x = hv0; st.y = hv1;
            *(float2*)(outbuf + ((size_t)t * BB + b0 + grp) * 64 + u) = st;
        }

        // publish h(t) into H[pp^1]
        {
            uint32_t hi, lo; split2(hv0, hv1, hi, lo);
            Hsm[pp ^ 1][0][grp * SWH + 4 * warp + qd] = hi;
            Hsm[pp ^ 1][1][grp * SWH + 4 * warp + qd] = lo;
        }

        // stage x(t+2) into ring slot t&1; prefetch x(t+3)
        const int t3 = (t + 3 < TT) ? t + 3 : TT - 1;
        if (INW == 64) {
            uint32_t hi, lo; split2(xc0, xc1, hi, lo);
            Xsm[t & 1][0][grp * SWX + 4 * warp + qd] = hi;
            Xsm[t & 1][1][grp * SWX + 4 * warp + qd] = lo;
            float2 v = *(const float2*)(xin + ((size_t)t3 * BB + b0 + grp) * 64 + u);
            xc0 = v.x; xc1 = v.y;
        } else if (tid < 64) {
            const int xr = tid >> 3, xw = tid & 7;
            uint32_t hi, lo; split2(xc0, xc1, hi, lo);
            Xsm[t & 1][0][xr * SWX + xw] = hi;
            Xsm[t & 1][1][xr * SWX + xw] = lo;
            float2 v = *(const float2*)(xin + ((size_t)(b0 + xr) * TT + t3) * 16 + 2 * xw);
            xc0 = v.x; xc1 = v.y;
        }

        // ---- slack region: x-mma for t+1 from ring slot (t+1)&1 ----
        // (slot written in step t-1 / prologue; visible since start-of-t sync)
        xR[0] = xR[1] = xR[2] = xR[3] = 0.f;
        xZ[0] = xZ[1] = xZ[2] = xZ[3] = 0.f;
        xN[0] = xN[1] = xN[2] = xN[3] = 0.f;
        xmma((t + 1) & 1, xR, xZ, xN);

        __syncthreads();
    }

    if (!WALL) {
        float2 st; st.x = hv0; st.y = hv1;
        *(float2*)(outbuf + (size_t)(b0 + grp) * 64 + u) = st;
    }
}

// ---------------------------------------------------------------------------
// Head: y[b] = fc2_b + fc2_w . relu(fc1_w @ h_last[b] + fc1_b)
// ---------------------------------------------------------------------------
__global__ void __launch_bounds__(256) head_kernel(
    const float* __restrict__ fc1w, const float* __restrict__ fc1b,
    const float* __restrict__ fc2w, const float* __restrict__ fc2b,
    float* __restrict__ y)
{
    __shared__ float s1[32 * 64];
    __shared__ float sb1[32];
    __shared__ float sw2[32];
    const int tid = threadIdx.x;
    for (int e = tid; e < 2048; e += 256) s1[e] = fc1w[e];
    if (tid < 32) { sb1[tid] = fc1b[tid]; sw2[tid] = fc2w[tid]; }
    __syncthreads();

    const int b = blockIdx.x * 256 + tid;
    const float* hp = g_hlast + (size_t)b * 64;
    float hv[64];
#pragma unroll
    for (int q = 0; q < 16; q++) {
        float4 v = *(const float4*)(hp + q * 4);
        hv[q * 4] = v.x; hv[q * 4 + 1] = v.y; hv[q * 4 + 2] = v.z; hv[q * 4 + 3] = v.w;
    }
    float acc = __ldg(fc2b);
#pragma unroll
    for (int j = 0; j < 32; j++) {
        float sacc = sb1[j];
#pragma unroll
        for (int k = 0; k < 64; k++) sacc = fmaf(s1[j * 64 + k], hv[k], sacc);
        acc = fmaf(sw2[j], fmaxf(sacc, 0.0f), acc);
    }
    y[b] = acc;
}

// ---------------------------------------------------------------------------
extern "C" void kernel_launch(void* const* d_in, const int* in_sizes, int n_in,
                              void* d_out, int out_size)
{
    const float* x    = (const float*)d_in[0];
    const float* Wih0 = (const float*)d_in[1];
    const float* Whh0 = (const float*)d_in[2];
    const float* bih0 = (const float*)d_in[3];
    const float* bhh0 = (const float*)d_in[4];
    const float* Wih1 = (const float*)d_in[5];
    const float* Whh1 = (const float*)d_in[6];
    const float* bih1 = (const float*)d_in[7];
    const float* bhh1 = (const float*)d_in[8];
    const float* Wih2 = (const float*)d_in[9];
    const float* Whh2 = (const float*)d_in[10];
    const float* bih2 = (const float*)d_in[11];
    const float* bhh2 = (const float*)d_in[12];
    const float* fc1w = (const float*)d_in[13];
    const float* fc1b = (const float*)d_in[14];
    const float* fc2w = (const float*)d_in[15];
    const float* fc2b = (const float*)d_in[16];
    float* y = (float*)d_out;
    (void)in_sizes; (void)n_in; (void)out_size;

    float *bufA = nullptr, *bufB = nullptr, *hlast = nullptr;
    cudaGetSymbolAddress((void**)&bufA, g_bufA);
    cudaGetSymbolAddress((void**)&bufB, g_bufB);
    cudaGetSymbolAddress((void**)&hlast, g_hlast);

    gru_hmma<16, 1><<<128, 256>>>(x,    Wih0, Whh0, bih0, bhh0, bufA);
    gru_hmma<64, 1><<<128, 256>>>(bufA, Wih1, Whh1, bih1, bhh1, bufB);
    gru_hmma<64, 0><<<128, 256>>>(bufB, Wih2, Whh2, bih2, bhh2, hlast);
    head_kernel<<<4, 256>>>(fc1w, fc1b, fc2w, fc2b, y);
}

// round 16
// speedup vs baseline: 4.1663x; 1.4052x over previous
#include <cuda_runtime.h>
#include <cuda_fp16.h>
#include <cstdint>

#define BB 1024
#define TT 512

// Scratch (device globals — allocation-free per harness rules)
__device__ float g_bufA[(size_t)TT * BB * 64];  // layer0 outputs [t][b][64]
__device__ float g_bufB[(size_t)TT * BB * 64];  // layer1 outputs [t][b][64]
__device__ float g_hlast[BB * 64];              // layer2 final h

__device__ __forceinline__ float fsigmoid(float x) {
    return __fdividef(1.0f, 1.0f + __expf(-x));
}
__device__ __forceinline__ float ftanhf(float x) {
    float e = __expf(2.0f * x);
    return 1.0f - __fdividef(2.0f, e + 1.0f);
}
__device__ __forceinline__ uint32_t smaddr(const void* p) {
    uint32_t a;
    asm("{ .reg .u64 t; cvta.to.shared.u64 t, %1; cvt.u32.u64 %0, t; }" : "=r"(a) : "l"(p));
    return a;
}
__device__ __forceinline__ uint32_t packh(float v0, float v1) {
    __half h0 = __float2half_rn(v0), h1 = __float2half_rn(v1);
    return ((uint32_t)__half_as_ushort(h1) << 16) | (uint32_t)__half_as_ushort(h0);
}
__device__ __forceinline__ void mma16816(float c[4], const uint32_t a[4], const uint32_t b[2]) {
    asm volatile(
        "mma.sync.aligned.m16n8k16.row.col.f32.f16.f16.f32 "
        "{%0,%1,%2,%3}, {%4,%5,%6,%7}, {%8,%9}, {%0,%1,%2,%3};"
        : "+f"(c[0]), "+f"(c[1]), "+f"(c[2]), "+f"(c[3])
        : "r"(a[0]), "r"(a[1]), "r"(a[2]), "r"(a[3]), "r"(b[0]), "r"(b[1]));
}
#define LDMX4(R, ADDR) \
    asm volatile("ldmatrix.sync.aligned.m8n8.x4.shared.b16 {%0,%1,%2,%3}, [%4];" \
        : "=r"((R)[0]), "=r"((R)[1]), "=r"((R)[2]), "=r"((R)[3]) : "r"(ADDR))

// ---------------------------------------------------------------------------
// HMMA fused GRU, single-plane fp16 (A and B), x-mma pipelined off the
// critical path. 128 blocks x 256 threads; block owns 8 batch rows.
// h ping-pong: Hsm[2][16*36]; x ring: Xsm[2][16*SWX] (2-deep, slot = t&1).
// Step t: h-mma (12) using xacc(t) from step t-1 -> update (h in regs) ->
// publish h(t) -> stage x(t+2) -> x-mma(t+1) -> sync.
// Per kstep per gate: ONE mma (fp16 A, fp16 B, f32 accumulate).
// INW = 16 (layer0: x is [b][t][16]) or 64 (prev layer [t][b][64]).
// WALL = 1: write all timesteps; 0: only final h.
// ---------------------------------------------------------------------------
template <int INW, int WALL>
__global__ void __launch_bounds__(256, 1) gru_hmma(
    const float* __restrict__ xin,
    const float* __restrict__ Wih, const float* __restrict__ Whh,
    const float* __restrict__ bih, const float* __restrict__ bhh,
    float* __restrict__ outbuf)
{
    constexpr int KSX = INW / 16;               // x k-steps: 4 or 1
    constexpr int SWH = 36;                     // h row stride (words)
    constexpr int SWX = (INW == 64) ? 36 : 12;  // x row stride (words)

    __shared__ uint32_t Hsm[2][16 * SWH];
    __shared__ uint32_t Xsm[2][16 * SWX];

    const int tid  = threadIdx.x;
    const int warp = tid >> 5;
    const int lane = tid & 31;
    const int grp  = lane >> 2;        // row 0..7 (also gate-col group for B)
    const int qd   = lane & 3;
    const int u    = 8 * warp + 2 * qd;
    const int b0   = blockIdx.x * 8;

    // ---- B fragments (fp16) in registers ----
    uint32_t bhh_f[3][4][2], bhx_f[3][KSX][2];
#pragma unroll
    for (int gi = 0; gi < 3; gi++) {
        const int g = gi * 64 + 8 * warp + grp;
        const int kk = 2 * qd;
#pragma unroll
        for (int ks = 0; ks < 4; ks++) {
            const float* src = Whh + (size_t)g * 64 + ks * 16;
            bhh_f[gi][ks][0] = packh(__ldg(src + kk),     __ldg(src + kk + 1));
            bhh_f[gi][ks][1] = packh(__ldg(src + kk + 8), __ldg(src + kk + 9));
        }
#pragma unroll
        for (int ks = 0; ks < KSX; ks++) {
            const float* src = Wih + (size_t)g * INW + ks * 16;
            bhx_f[gi][ks][0] = packh(__ldg(src + kk),     __ldg(src + kk + 1));
            bhx_f[gi][ks][1] = packh(__ldg(src + kk + 8), __ldg(src + kk + 9));
        }
    }

    // biases for owned units u, u+1
    const float bRv0 = __ldg(bih + u)       + __ldg(bhh + u);
    const float bRv1 = __ldg(bih + u + 1)   + __ldg(bhh + u + 1);
    const float bZv0 = __ldg(bih + 64 + u)  + __ldg(bhh + 64 + u);
    const float bZv1 = __ldg(bih + 65 + u)  + __ldg(bhh + 65 + u);
    const float bNx0 = __ldg(bih + 128 + u), bNx1 = __ldg(bih + 129 + u);
    const float bNh0 = __ldg(bhh + 128 + u), bNh1 = __ldg(bhh + 129 + u);

    // zero H (both parities; rows 8-15 stay zero) and X ring
    for (int e = tid; e < 2 * 16 * SWH; e += 256) (&Hsm[0][0])[e] = 0u;
    for (int e = tid; e < 2 * 16 * SWX; e += 256) (&Xsm[0][0])[e] = 0u;

    // ldmatrix per-lane addresses
    uint32_t hab[2], xab[2];
#pragma unroll
    for (int pp = 0; pp < 2; pp++) {
        hab[pp] = smaddr(&Hsm[pp][0]) + (lane & 15) * (SWH * 4) + (lane >> 4) * 16;
        xab[pp] = smaddr(&Xsm[pp][0]) + (lane & 15) * (SWX * 4) + (lane >> 4) * 16;
    }
    __syncthreads();

    // ---- stage x(0)->slot0, x(1)->slot1; prefetch x(2) ----
    float xc0 = 0.0f, xc1 = 0.0f;
    if (INW == 64) {
#pragma unroll
        for (int sl = 0; sl < 2; sl++) {
            float2 v = *(const float2*)(xin + ((size_t)sl * BB + b0 + grp) * 64 + u);
            Xsm[sl][grp * SWX + 4 * warp + qd] = packh(v.x, v.y);
        }
        float2 v = *(const float2*)(xin + ((size_t)2 * BB + b0 + grp) * 64 + u);
        xc0 = v.x; xc1 = v.y;
    } else if (tid < 64) {
        const int xr = tid >> 3, xw = tid & 7;
#pragma unroll
        for (int sl = 0; sl < 2; sl++) {
            float2 v = *(const float2*)(xin + ((size_t)(b0 + xr) * TT + sl) * 16 + 2 * xw);
            Xsm[sl][xr * SWX + xw] = packh(v.x, v.y);
        }
        float2 v = *(const float2*)(xin + ((size_t)(b0 + xr) * TT + 2) * 16 + 2 * xw);
        xc0 = v.x; xc1 = v.y;
    }
    __syncthreads();

    // x-mma over one ring slot -> accumulators
    auto xmma = [&](int slot, float xR[4], float xZ[4], float xN[4]) {
#pragma unroll
        for (int ks = 0; ks < KSX; ks++) {
            uint32_t ah[4];
            LDMX4(ah, xab[slot] + ks * 32);
            mma16816(xR, ah, bhx_f[0][ks]);
            mma16816(xZ, ah, bhx_f[1][ks]);
            mma16816(xN, ah, bhx_f[2][ks]);
        }
    };

    float xR[4] = {0,0,0,0}, xZ[4] = {0,0,0,0}, xN[4] = {0,0,0,0};
    xmma(0, xR, xZ, xN);               // xacc for t=0

    float hv0 = 0.0f, hv1 = 0.0f;

#pragma unroll 1
    for (int t = 0; t < TT; ++t) {
        const int pp = t & 1;

        // ---- h-mma (critical path): 12 mma ----
        float cR[4]  = {xR[0], xR[1], xR[2], xR[3]};
        float cZ[4]  = {xZ[0], xZ[1], xZ[2], xZ[3]};
        float cNh[4] = {0.f, 0.f, 0.f, 0.f};
#pragma unroll
        for (int ks = 0; ks < 4; ks++) {
            uint32_t ah[4];
            LDMX4(ah, hab[pp] + ks * 32);
            mma16816(cR, ah, bhh_f[0][ks]);
            mma16816(cZ, ah, bhh_f[1][ks]);
            mma16816(cNh, ah, bhh_f[2][ks]);
        }

        // ---- update: thread owns (row grp, units u,u+1); h in registers ----
        float r0 = fsigmoid(cR[0] + bRv0), r1 = fsigmoid(cR[1] + bRv1);
        float z0 = fsigmoid(cZ[0] + bZv0), z1 = fsigmoid(cZ[1] + bZv1);
        float n0 = ftanhf(xN[0] + bNx0 + r0 * (cNh[0] + bNh0));
        float n1 = ftanhf(xN[1] + bNx1 + r1 * (cNh[1] + bNh1));
        hv0 = n0 + z0 * (hv0 - n0);
        hv1 = n1 + z1 * (hv1 - n1);

        if (WALL) {
            float2 st; st.x = hv0; st.y = hv1;
            *(float2*)(outbuf + ((size_t)t * BB + b0 + grp) * 64 + u) = st;
        }

        // publish h(t) into H[pp^1]
        Hsm[pp ^ 1][grp * SWH + 4 * warp + qd] = packh(hv0, hv1);

        // stage x(t+2) into ring slot t&1; prefetch x(t+3)
        const int t3 = (t + 3 < TT) ? t + 3 : TT - 1;
        if (INW == 64) {
            Xsm[t & 1][grp * SWX + 4 * warp + qd] = packh(xc0, xc1);
            float2 v = *(const float2*)(xin + ((size_t)t3 * BB + b0 + grp) * 64 + u);
            xc0 = v.x; xc1 = v.y;
        } else if (tid < 64) {
            const int xr = tid >> 3, xw = tid & 7;
            Xsm[t & 1][xr * SWX + xw] = packh(xc0, xc1);
            float2 v = *(const float2*)(xin + ((size_t)(b0 + xr) * TT + t3) * 16 + 2 * xw);
            xc0 = v.x; xc1 = v.y;
        }

        // ---- slack region: x-mma for t+1 from ring slot (t+1)&1 ----
        xR[0] = xR[1] = xR[2] = xR[3] = 0.f;
        xZ[0] = xZ[1] = xZ[2] = xZ[3] = 0.f;
        xN[0] = xN[1] = xN[2] = xN[3] = 0.f;
        xmma((t + 1) & 1, xR, xZ, xN);

        __syncthreads();
    }

    if (!WALL) {
        float2 st; st.x = hv0; st.y = hv1;
        *(float2*)(outbuf + (size_t)(b0 + grp) * 64 + u) = st;
    }
}

// ---------------------------------------------------------------------------
// Head: y[b] = fc2_b + fc2_w . relu(fc1_w @ h_last[b] + fc1_b)
// ---------------------------------------------------------------------------
__global__ void __launch_bounds__(256) head_kernel(
    const float* __restrict__ fc1w, const float* __restrict__ fc1b,
    const float* __restrict__ fc2w, const float* __restrict__ fc2b,
    float* __restrict__ y)
{
    __shared__ float s1[32 * 64];
    __shared__ float sb1[32];
    __shared__ float sw2[32];
    const int tid = threadIdx.x;
    for (int e = tid; e < 2048; e += 256) s1[e] = fc1w[e];
    if (tid < 32) { sb1[tid] = fc1b[tid]; sw2[tid] = fc2w[tid]; }
    __syncthreads();

    const int b = blockIdx.x * 256 + tid;
    const float* hp = g_hlast + (size_t)b * 64;
    float hv[64];
#pragma unroll
    for (int q = 0; q < 16; q++) {
        float4 v = *(const float4*)(hp + q * 4);
        hv[q * 4] = v.x; hv[q * 4 + 1] = v.y; hv[q * 4 + 2] = v.z; hv[q * 4 + 3] = v.w;
    }
    float acc = __ldg(fc2b);
#pragma unroll
    for (int j = 0; j < 32; j++) {
        float sacc = sb1[j];
#pragma unroll
        for (int k = 0; k < 64; k++) sacc = fmaf(s1[j * 64 + k], hv[k], sacc);
        acc = fmaf(sw2[j], fmaxf(sacc, 0.0f), acc);
    }
    y[b] = acc;
}

// ---------------------------------------------------------------------------
extern "C" void kernel_launch(void* const* d_in, const int* in_sizes, int n_in,
                              void* d_out, int out_size)
{
    const float* x    = (const float*)d_in[0];
    const float* Wih0 = (const float*)d_in[1];
    const float* Whh0 = (const float*)d_in[2];
    const float* bih0 = (const float*)d_in[3];
    const float* bhh0 = (const float*)d_in[4];
    const float* Wih1 = (const float*)d_in[5];
    const float* Whh1 = (const float*)d_in[6];
    const float* bih1 = (const float*)d_in[7];
    const float* bhh1 = (const float*)d_in[8];
    const float* Wih2 = (const float*)d_in[9];
    const float* Whh2 = (const float*)d_in[10];
    const float* bih2 = (const float*)d_in[11];
    const float* bhh2 = (const float*)d_in[12];
    const float* fc1w = (const float*)d_in[13];
    const float* fc1b = (const float*)d_in[14];
    const float* fc2w = (const float*)d_in[15];
    const float* fc2b = (const float*)d_in[16];
    float* y = (float*)d_out;
    (void)in_sizes; (void)n_in; (void)out_size;

    float *bufA = nullptr, *bufB = nullptr, *hlast = nullptr;
    cudaGetSymbolAddress((void**)&bufA, g_bufA);
    cudaGetSymbolAddress((void**)&bufB, g_bufB);
    cudaGetSymbolAddress((void**)&hlast, g_hlast);

    gru_hmma<16, 1><<<128, 256>>>(x,    Wih0, Whh0, bih0, bhh0, bufA);
    gru_hmma<64, 1><<<128, 256>>>(bufA, Wih1, Whh1, bih1, bhh1, bufB);
    gru_hmma<64, 0><<<128, 256>>>(bufB, Wih2, Whh2, bih2, bhh2, hlast);
    head_kernel<<<4, 256>>>(fc1w, fc1b, fc2w, fc2b, y);
}

// round 17
// speedup vs baseline: 4.4969x; 1.0794x over previous
#include <cuda_runtime.h>
#include <cuda_fp16.h>
#include <cstdint>

#define BB 1024
#define TT 512

// Scratch (device globals — allocation-free per harness rules)
__device__ float g_bufA[(size_t)TT * BB * 64];  // layer0 outputs [t][b][64]
__device__ float g_bufB[(size_t)TT * BB * 64];  // layer1 outputs [t][b][64]
__device__ float g_hlast[BB * 64];              // layer2 final h

__device__ __forceinline__ float fsigmoid(float x) {
    return __fdividef(1.0f, 1.0f + __expf(-x));
}
__device__ __forceinline__ float ftanhf(float x) {
    float e = __expf(2.0f * x);
    return 1.0f - __fdividef(2.0f, e + 1.0f);
}
__device__ __forceinline__ uint32_t smaddr(const void* p) {
    uint32_t a;
    asm("{ .reg .u64 t; cvta.to.shared.u64 t, %1; cvt.u32.u64 %0, t; }" : "=r"(a) : "l"(p));
    return a;
}
__device__ __forceinline__ uint32_t packh(float v0, float v1) {
    __half h0 = __float2half_rn(v0), h1 = __float2half_rn(v1);
    return ((uint32_t)__half_as_ushort(h1) << 16) | (uint32_t)__half_as_ushort(h0);
}
__device__ __forceinline__ void mma16816(float c[4], const uint32_t a[4], const uint32_t b[2]) {
    asm volatile(
        "mma.sync.aligned.m16n8k16.row.col.f32.f16.f16.f32 "
        "{%0,%1,%2,%3}, {%4,%5,%6,%7}, {%8,%9}, {%0,%1,%2,%3};"
        : "+f"(c[0]), "+f"(c[1]), "+f"(c[2]), "+f"(c[3])
        : "r"(a[0]), "r"(a[1]), "r"(a[2]), "r"(a[3]), "r"(b[0]), "r"(b[1]));
}
#define LDMX4(R, ADDR) \
    asm volatile("ldmatrix.sync.aligned.m8n8.x4.shared.b16 {%0,%1,%2,%3}, [%4];" \
        : "=r"((R)[0]), "=r"((R)[1]), "=r"((R)[2]), "=r"((R)[3]) : "r"(ADDR))

// ---------------------------------------------------------------------------
// HMMA fused GRU, fp16 single-plane, TIME-PAIRED x-projection.
// 128 blocks x 256 threads; block owns 8 batch rows.
// x-projection uses the full M=16: Xsm slot holds x(2j) in rows 0-7 and
// x(2j+1) in rows 8-15, so ONE x-mma pass projects two timesteps:
// C c[0..1] -> even step, c[2..3] -> odd step. x-mma runs once per 2 steps
// (during the odd step), cutting mma/warp/step from 24 to 18.
// h ping-pong: Hsm[t&1] read, h(t) published to Hsm[(t&1)^1].
// Ring: slot for pair j staged during odd step 2j-3... staged >=2 barriers
// before its xmma read; staging and reading always touch opposite slots.
// INW = 16 (layer0: x is [b][t][16]) or 64 (prev layer [t][b][64]).
// WALL = 1: write all timesteps; 0: only final h.
// ---------------------------------------------------------------------------
template <int INW, int WALL>
__global__ void __launch_bounds__(256, 1) gru_hmma(
    const float* __restrict__ xin,
    const float* __restrict__ Wih, const float* __restrict__ Whh,
    const float* __restrict__ bih, const float* __restrict__ bhh,
    float* __restrict__ outbuf)
{
    constexpr int KSX = INW / 16;               // x k-steps: 4 or 1
    constexpr int SWH = 36;                     // h row stride (words)
    constexpr int SWX = (INW == 64) ? 36 : 12;  // x row stride (words)

    __shared__ uint32_t Hsm[2][16 * SWH];
    __shared__ uint32_t Xsm[2][16 * SWX];

    const int tid  = threadIdx.x;
    const int warp = tid >> 5;
    const int lane = tid & 31;
    const int grp  = lane >> 2;        // row 0..7 (also gate-col group for B)
    const int qd   = lane & 3;
    const int u    = 8 * warp + 2 * qd;
    const int b0   = blockIdx.x * 8;

    // ---- B fragments (fp16) in registers ----
    uint32_t bhh_f[3][4][2], bhx_f[3][KSX][2];
#pragma unroll
    for (int gi = 0; gi < 3; gi++) {
        const int g = gi * 64 + 8 * warp + grp;
        const int kk = 2 * qd;
#pragma unroll
        for (int ks = 0; ks < 4; ks++) {
            const float* src = Whh + (size_t)g * 64 + ks * 16;
            bhh_f[gi][ks][0] = packh(__ldg(src + kk),     __ldg(src + kk + 1));
            bhh_f[gi][ks][1] = packh(__ldg(src + kk + 8), __ldg(src + kk + 9));
        }
#pragma unroll
        for (int ks = 0; ks < KSX; ks++) {
            const float* src = Wih + (size_t)g * INW + ks * 16;
            bhx_f[gi][ks][0] = packh(__ldg(src + kk),     __ldg(src + kk + 1));
            bhx_f[gi][ks][1] = packh(__ldg(src + kk + 8), __ldg(src + kk + 9));
        }
    }

    // biases for owned units u, u+1
    const float bRv0 = __ldg(bih + u)       + __ldg(bhh + u);
    const float bRv1 = __ldg(bih + u + 1)   + __ldg(bhh + u + 1);
    const float bZv0 = __ldg(bih + 64 + u)  + __ldg(bhh + 64 + u);
    const float bZv1 = __ldg(bih + 65 + u)  + __ldg(bhh + 65 + u);
    const float bNx0 = __ldg(bih + 128 + u), bNx1 = __ldg(bih + 129 + u);
    const float bNh0 = __ldg(bhh + 128 + u), bNh1 = __ldg(bhh + 129 + u);

    // zero H (both parities; rows 8-15 stay zero)
    for (int e = tid; e < 2 * 16 * SWH; e += 256) (&Hsm[0][0])[e] = 0u;

    // ldmatrix per-lane addresses
    uint32_t hab[2], xab[2];
#pragma unroll
    for (int pp = 0; pp < 2; pp++) {
        hab[pp] = smaddr(&Hsm[pp][0]) + (lane & 15) * (SWH * 4) + (lane >> 4) * 16;
        xab[pp] = smaddr(&Xsm[pp][0]) + (lane & 15) * (SWX * 4) + (lane >> 4) * 16;
    }

    // x loader: pair P -> (even=2P, odd=2P+1), per-thread share into 4 floats
    auto xload = [&](int P, float v[4]) {
        const int te = (2 * P < TT) ? 2 * P : TT - 1;
        const int to = (2 * P + 1 < TT) ? 2 * P + 1 : TT - 1;
        if (INW == 64) {
            float2 a = *(const float2*)(xin + ((size_t)te * BB + b0 + grp) * 64 + u);
            float2 b = *(const float2*)(xin + ((size_t)to * BB + b0 + grp) * 64 + u);
            v[0] = a.x; v[1] = a.y; v[2] = b.x; v[3] = b.y;
        } else if (tid < 128) {
            const int r16 = tid >> 3, xw = tid & 7;
            const int row = r16 & 7, tt = (r16 >> 3) ? to : te;
            float2 a = *(const float2*)(xin + ((size_t)(b0 + row) * TT + tt) * 16 + 2 * xw);
            v[0] = a.x; v[1] = a.y;
        }
    };
    // x stager: per-thread share -> slot (even rows 0-7, odd rows 8-15)
    auto xstage = [&](int slot, const float v[4]) {
        if (INW == 64) {
            Xsm[slot][grp * SWX + 4 * warp + qd]       = packh(v[0], v[1]);
            Xsm[slot][(grp + 8) * SWX + 4 * warp + qd] = packh(v[2], v[3]);
        } else if (tid < 128) {
            const int r16 = tid >> 3, xw = tid & 7;
            Xsm[slot][r16 * SWX + xw] = packh(v[0], v[1]);
        }
    };
    // x-mma over one slot: accumulates both timesteps of the pair
    auto xmma = [&](int slot, float xR[4], float xZ[4], float xN[4]) {
#pragma unroll
        for (int ks = 0; ks < KSX; ks++) {
            uint32_t ah[4];
            LDMX4(ah, xab[slot] + ks * 32);
            mma16816(xR, ah, bhx_f[0][ks]);
            mma16816(xZ, ah, bhx_f[1][ks]);
            mma16816(xN, ah, bhx_f[2][ks]);
        }
    };

    // ---- prologue: stage pair0->slot0, pair1->slot1; carry pair2 in regs ----
    float xc[4] = {0, 0, 0, 0}, xp[4] = {0, 0, 0, 0};
    {
        float v0[4] = {0, 0, 0, 0}, v1[4] = {0, 0, 0, 0};
        xload(0, v0); xload(1, v1);
        xstage(0, v0); xstage(1, v1);
        xload(2, xc);
    }
    __syncthreads();

    float xR[4] = {0, 0, 0, 0}, xZ[4] = {0, 0, 0, 0}, xN[4] = {0, 0, 0, 0};
    xmma(0, xR, xZ, xN);               // xacc for pair 0 (t=0,1)

    float hv0 = 0.0f, hv1 = 0.0f;

#pragma unroll 1
    for (int j = 0; j < TT / 2; ++j) {
        // ================= EVEN step t = 2j (H parity 0) =================
        {
            float cR[4]  = {xR[0], xR[1], 0.f, 0.f};
            float cZ[4]  = {xZ[0], xZ[1], 0.f, 0.f};
            float cNh[4] = {0.f, 0.f, 0.f, 0.f};
#pragma unroll
            for (int ks = 0; ks < 4; ks++) {
                uint32_t ah[4];
                LDMX4(ah, hab[0] + ks * 32);
                mma16816(cR, ah, bhh_f[0][ks]);
                mma16816(cZ, ah, bhh_f[1][ks]);
                mma16816(cNh, ah, bhh_f[2][ks]);
            }
            float r0 = fsigmoid(cR[0] + bRv0), r1 = fsigmoid(cR[1] + bRv1);
            float z0 = fsigmoid(cZ[0] + bZv0), z1 = fsigmoid(cZ[1] + bZv1);
            float n0 = ftanhf(xN[0] + bNx0 + r0 * (cNh[0] + bNh0));
            float n1 = ftanhf(xN[1] + bNx1 + r1 * (cNh[1] + bNh1));
            hv0 = n0 + z0 * (hv0 - n0);
            hv1 = n1 + z1 * (hv1 - n1);
            if (WALL) {
                float2 st; st.x = hv0; st.y = hv1;
                *(float2*)(outbuf + ((size_t)(2 * j) * BB + b0 + grp) * 64 + u) = st;
            }
            Hsm[1][grp * SWH + 4 * warp + qd] = packh(hv0, hv1);

            xload(j + 3, xp);          // prefetch pair j+3 (used next odd step)
            __syncthreads();
        }
        // ================= ODD step t = 2j+1 (H parity 1) =================
        {
            float cR[4]  = {xR[2], xR[3], 0.f, 0.f};
            float cZ[4]  = {xZ[2], xZ[3], 0.f, 0.f};
            float cNh[4] = {0.f, 0.f, 0.f, 0.f};
#pragma unroll
            for (int ks = 0; ks < 4; ks++) {
                uint32_t ah[4];
                LDMX4(ah, hab[1] + ks * 32);
                mma16816(cR, ah, bhh_f[0][ks]);
                mma16816(cZ, ah, bhh_f[1][ks]);
                mma16816(cNh, ah, bhh_f[2][ks]);
            }
            float r0 = fsigmoid(cR[0] + bRv0), r1 = fsigmoid(cR[1] + bRv1);
            float z0 = fsigmoid(cZ[0] + bZv0), z1 = fsigmoid(cZ[1] + bZv1);
            float n0 = ftanhf(xN[2] + bNx0 + r0 * (cNh[0] + bNh0));
            float n1 = ftanhf(xN[3] + bNx1 + r1 * (cNh[1] + bNh1));
            hv0 = n0 + z0 * (hv0 - n0);
            hv1 = n1 + z1 * (hv1 - n1);
            if (WALL) {
                float2 st; st.x = hv0; st.y = hv1;
                *(float2*)(outbuf + ((size_t)(2 * j + 1) * BB + b0 + grp) * 64 + u) = st;
            }
            Hsm[0][grp * SWH + 4 * warp + qd] = packh(hv0, hv1);

            // stage pair j+2 into slot j&1 (its last reader was odd step 2j-1)
            xstage(j & 1, xc);
#pragma unroll
            for (int q = 0; q < 4; q++) xc[q] = xp[q];

            // x-mma for pair j+1 from slot (j+1)&1 (staged at odd step 2j-1)
            xR[0] = xR[1] = xR[2] = xR[3] = 0.f;
            xZ[0] = xZ[1] = xZ[2] = xZ[3] = 0.f;
            xN[0] = xN[1] = xN[2] = xN[3] = 0.f;
            xmma((j + 1) & 1, xR, xZ, xN);

            __syncthreads();
        }
    }

    if (!WALL) {
        float2 st; st.x = hv0; st.y = hv1;
        *(float2*)(outbuf + (size_t)(b0 + grp) * 64 + u) = st;
    }
}

// ---------------------------------------------------------------------------
// Head: y[b] = fc2_b + fc2_w . relu(fc1_w @ h_last[b] + fc1_b)
// ---------------------------------------------------------------------------
__global__ void __launch_bounds__(256) head_kernel(
    const float* __restrict__ fc1w, const float* __restrict__ fc1b,
    const float* __restrict__ fc2w, const float* __restrict__ fc2b,
    float* __restrict__ y)
{
    __shared__ float s1[32 * 64];
    __shared__ float sb1[32];
    __shared__ float sw2[32];
    const int tid = threadIdx.x;
    for (int e = tid; e < 2048; e += 256) s1[e] = fc1w[e];
    if (tid < 32) { sb1[tid] = fc1b[tid]; sw2[tid] = fc2w[tid]; }
    __syncthreads();

    const int b = blockIdx.x * 256 + tid;
    const float* hp = g_hlast + (size_t)b * 64;
    float hv[64];
#pragma unroll
    for (int q = 0; q < 16; q++) {
        float4 v = *(const float4*)(hp + q * 4);
        hv[q * 4] = v.x; hv[q * 4 + 1] = v.y; hv[q * 4 + 2] = v.z; hv[q * 4 + 3] = v.w;
    }
    float acc = __ldg(fc2b);
#pragma unroll
    for (int j = 0; j < 32; j++) {
        float sacc = sb1[j];
#pragma unroll
        for (int k = 0; k < 64; k++) sacc = fmaf(s1[j * 64 + k], hv[k], sacc);
        acc = fmaf(sw2[j], fmaxf(sacc, 0.0f), acc);
    }
    y[b] = acc;
}

// ---------------------------------------------------------------------------
extern "C" void kernel_launch(void* const* d_in, const int* in_sizes, int n_in,
                              void* d_out, int out_size)
{
    const float* x    = (const float*)d_in[0];
    const float* Wih0 = (const float*)d_in[1];
    const float* Whh0 = (const float*)d_in[2];
    const float* bih0 = (const float*)d_in[3];
    const float* bhh0 = (const float*)d_in[4];
    const float* Wih1 = (const float*)d_in[5];
    const float* Whh1 = (const float*)d_in[6];
    const float* bih1 = (const float*)d_in[7];
    const float* bhh1 = (const float*)d_in[8];
    const float* Wih2 = (const float*)d_in[9];
    const float* Whh2 = (const float*)d_in[10];
    const float* bih2 = (const float*)d_in[11];
    const float* bhh2 = (const float*)d_in[12];
    const float* fc1w = (const float*)d_in[13];
    const float* fc1b = (const float*)d_in[14];
    const float* fc2w = (const float*)d_in[15];
    const float* fc2b = (const float*)d_in[16];
    float* y = (float*)d_out;
    (void)in_sizes; (void)n_in; (void)out_size;

    float *bufA = nullptr, *bufB = nullptr, *hlast = nullptr;
    cudaGetSymbolAddress((void**)&bufA, g_bufA);
    cudaGetSymbolAddress((void**)&bufB, g_bufB);
    cudaGetSymbolAddress((void**)&hlast, g_hlast);

    gru_hmma<16, 1><<<128, 256>>>(x,    Wih0, Whh0, bih0, bhh0, bufA);
    gru_hmma<64, 1><<<128, 256>>>(bufA, Wih1, Whh1, bih1, bhh1, bufB);
    gru_hmma<64, 0><<<128, 256>>>(bufB, Wih2, Whh2, bih2, bhh2, hlast);
    head_kernel<<<4, 256>>>(fc1w, fc1b, fc2w, fc2b, y);
}